// round 14
// baseline (speedup 1.0000x reference)
#include <cuda_runtime.h>
#include <cuda_bf16.h>
#include <cuda_fp16.h>
#include <math.h>
#include <stdint.h>

// ---------------- problem constants ----------------
#define BATCH 128
#define SEGS  196
#define HW    224
#define NPIX  (HW*HW)
#define M_ROWS (BATCH*SEGS)      // 25088 = 128*196
#define BN_EPS 1e-5f
#define OUT_SLICED_ELEMS ((size_t)BATCH*NPIX)

// ================= helpers =================
__device__ __forceinline__ uint32_t smem_u32(const void* p) {
    uint32_t a;
    asm("{ .reg .u64 t; cvta.to.shared.u64 t, %1; cvt.u32.u64 %0, t; }" : "=r"(a) : "l"(p));
    return a;
}
#define SWZ128(off) ((off) ^ (((off) >> 3) & 0x70))

#define CP_ASYNC16(saddr, gptr) \
    asm volatile("cp.async.cg.shared.global [%0], [%1], 16;" :: "r"(saddr), "l"(gptr))
#define CP_COMMIT() asm volatile("cp.async.commit_group;" ::: "memory")
#define CP_WAIT0()  asm volatile("cp.async.wait_group 0;" ::: "memory")
#define CP_WAIT2()  asm volatile("cp.async.wait_group 2;" ::: "memory")

#define LDSM_X4(r, addr) \
    asm volatile("ldmatrix.sync.aligned.m8n8.x4.shared.b16 {%0,%1,%2,%3}, [%4];" \
        : "=r"((r)[0]), "=r"((r)[1]), "=r"((r)[2]), "=r"((r)[3]) : "r"(addr))

__device__ __forceinline__ void mma_f16(float* c, const uint32_t* a, const uint32_t* b) {
    asm volatile(
        "mma.sync.aligned.m16n8k16.row.col.f32.f16.f16.f32 "
        "{%0,%1,%2,%3}, {%4,%5,%6,%7}, {%8,%9}, {%0,%1,%2,%3};"
        : "+f"(c[0]), "+f"(c[1]), "+f"(c[2]), "+f"(c[3])
        : "r"(a[0]), "r"(a[1]), "r"(a[2]), "r"(a[3]), "r"(b[0]), "r"(b[1]));
}

__device__ __forceinline__ void split_fp16(float v, uint16_t& h, uint16_t& l) {
    __half hb = __float2half_rn(v);
    __half lb = __float2half_rn(v - __half2float(hb));
    h = __half_as_ushort(hb);
    l = __half_as_ushort(lb);
}

// ================= scratch (device globals) =================
__device__ float g_acc[9 * M_ROWS];
__device__ __half g_hi0[(size_t)M_ROWS * 768];
__device__ __half g_lo0[(size_t)M_ROWS * 768];
__device__ __half g_hi1[(size_t)M_ROWS * 768];
__device__ __half g_lo1[(size_t)M_ROWS * 768];
__device__ __half g_wh[999424];
__device__ float g_scale[2208];
__device__ float g_shift[2208];

// ================= segment accumulation =================
__global__ __launch_bounds__(256) void seg_acc_kernel(
    const float* __restrict__ x, const int* __restrict__ sliced,
    float* __restrict__ outSliced, float* __restrict__ acc)
{
    __shared__ float s[SEGS * 9];
    const int b = blockIdx.y;
    for (int i = threadIdx.x; i < SEGS * 9; i += blockDim.x) s[i] = 0.0f;
    __syncthreads();

    const int chunk = NPIX / gridDim.x;
    const int p0 = blockIdx.x * chunk;
    const float* xb = x + (size_t)b * 3 * NPIX;
    const int* sb = sliced + (size_t)b * NPIX;
    float* ob = outSliced + (size_t)b * NPIX;

    for (int p = p0 + threadIdx.x; p < p0 + chunk; p += blockDim.x) {
        int sid = sb[p];
        ob[p] = (float)sid;
        float r = (float)(p / HW);
        float c = (float)(p % HW);
        float v0 = xb[p], v1 = xb[NPIX + p], v2 = xb[2 * NPIX + p];
        float* a9 = s + sid * 9;
        atomicAdd(a9 + 0, 1.0f);
        atomicAdd(a9 + 1, r);
        atomicAdd(a9 + 2, c);
        atomicAdd(a9 + 3, v0);
        atomicAdd(a9 + 4, v1);
        atomicAdd(a9 + 5, v2);
        atomicAdd(a9 + 6, v0 * v0);
        atomicAdd(a9 + 7, v1 * v1);
        atomicAdd(a9 + 8, v2 * v2);
    }
    __syncthreads();
    for (int i = threadIdx.x; i < SEGS * 9; i += blockDim.x) {
        int sid = i / 9, f = i % 9;
        float v = s[i];
        if (v != 0.0f) atomicAdd(&acc[(size_t)f * M_ROWS + b * SEGS + sid], v);
    }
}

// ================= fused finalize + weight/BN prep =================
struct PrepArgs {
    const float* w[5];
    const float* bb[5];
    const float* g[5];
    const float* be[5];
    const float* rm[5];
    const float* rv[5];
};

__global__ __launch_bounds__(256) void finprep_kernel(
    PrepArgs a, const float* __restrict__ acc, const float* __restrict__ x,
    __half* __restrict__ fhi, __half* __restrict__ flo,
    __half* __restrict__ wh,
    float* __restrict__ sc, float* __restrict__ sh)
{
    const int NLc[5] = {96, 192, 384, 768, 768};
    const int KLc[5] = {11, 96, 192, 384, 768};
    const int KPc[5] = {64, 128, 192, 384, 768};
    const int WOFFc[6] = {0, 8192, 40960, 114688, 409600, 999424};
    const int SOFFc[6] = {0, 96, 288, 672, 1440, 2208};

    const int stride = gridDim.x * blockDim.x;
    const int tid0 = blockIdx.x * blockDim.x + threadIdx.x;

    for (int idx = tid0; idx < M_ROWS; idx += stride) {
        int b = idx / SEGS;
        float cnt  = acc[idx];
        float inv  = 1.0f / fmaxf(cnt, 1.0f);
        float mrow = acc[(size_t)1 * M_ROWS + idx] * inv;
        float mcol = acc[(size_t)2 * M_ROWS + idx] * inv;
        float m0 = acc[(size_t)3 * M_ROWS + idx] * inv;
        float m1 = acc[(size_t)4 * M_ROWS + idx] * inv;
        float m2 = acc[(size_t)5 * M_ROWS + idx] * inv;
        float dn = 1.0f / fmaxf(cnt - 1.0f, 1.0f);
        float v0 = (acc[(size_t)6 * M_ROWS + idx] - cnt * m0 * m0) * dn;
        float v1 = (acc[(size_t)7 * M_ROWS + idx] - cnt * m1 * m1) * dn;
        float v2 = (acc[(size_t)8 * M_ROWS + idx] - cnt * m2 * m2) * dn;
        float sd0 = (cnt > 1.0f) ? sqrtf(fmaxf(v0, 0.0f)) : 0.0f;
        float sd1 = (cnt > 1.0f) ? sqrtf(fmaxf(v1, 0.0f)) : 0.0f;
        float sd2 = (cnt > 1.0f) ? sqrtf(fmaxf(v2, 0.0f)) : 0.0f;

        int ri = min(max((int)mrow, 0), HW - 1);
        int ci = min(max((int)mcol, 0), HW - 1);
        const float* xb = x + (size_t)b * 3 * NPIX;
        int pp = ri * HW + ci;
        float mask = (cnt > 0.0f) ? 1.0f : 0.0f;

        float f[11];
        f[0] = mrow * mask; f[1] = mcol * mask;
        f[2] = m0 * mask;   f[3] = m1 * mask;   f[4] = m2 * mask;
        f[5] = sd0 * mask;  f[6] = sd1 * mask;  f[7] = sd2 * mask;
        f[8] = xb[pp] * mask; f[9] = xb[NPIX + pp] * mask; f[10] = xb[2 * NPIX + pp] * mask;

        __half* ph = fhi + (size_t)idx * 64;
        __half* pl = flo + (size_t)idx * 64;
        #pragma unroll
        for (int c = 0; c < 11; c++) {
            __half h = __float2half_rn(f[c]);
            ph[c] = h;
            pl[c] = __float2half_rn(f[c] - __half2float(h));
        }
        for (int c = 11; c < 64; c++) { ph[c] = __float2half_rn(0.f); pl[c] = __float2half_rn(0.f); }
    }

    for (int i = tid0; i < 999424; i += stride) {
        int L = 0;
        while (i >= WOFFc[L + 1]) L++;
        int off = i - WOFFc[L];
        int n = off / KPc[L], k = off - n * KPc[L];
        float v = (n < NLc[L] && k < KLc[L]) ? a.w[L][n * KLc[L] + k] : 0.0f;
        wh[i] = __float2half_rn(v);
    }
    for (int i = tid0; i < 2208; i += stride) {
        int L = 0;
        while (i >= SOFFc[L + 1]) L++;
        int n = i - SOFFc[L];
        float s = a.g[L][n] * rsqrtf(a.rv[L][n] + BN_EPS);
        sc[i] = s;
        sh[i] = (a.bb[L][n] - a.rm[L][n]) * s + a.be[L][n];
    }
}

// ================= fused L0+L1 kernel (fp16 2-product, unchanged) =================
__global__ __launch_bounds__(512, 1) void fused01_kernel(
    const __half* __restrict__ Fhi, const __half* __restrict__ Flo,
    const __half* __restrict__ W0h, const __half* __restrict__ W1h,
    const float* __restrict__ scAll, const float* __restrict__ shAll,
    __half* __restrict__ Ohi, __half* __restrict__ Olo)
{
    extern __shared__ __align__(1024) char smem[];
    const uint32_t sbase = smem_u32(smem);
    const int tid = threadIdx.x;
    const int wid = tid >> 5;
    const int lane = tid & 31;
    const int wm = wid & 7;
    const int wn = wid >> 3;
    const int bm = blockIdx.y * 256;

    const uint32_t F_AH = sbase, F_AL = sbase + 32768;
    const uint32_t W0H = sbase + 65536;
    const uint32_t AC0H = sbase + 98304, AC0L = sbase + 163840;
    const uint32_t W1H = sbase;

    #pragma unroll
    for (int it = 0; it < 4; it++) {
        int i = tid + it * 512;
        int r = i >> 3, cc = i & 7;
        uint32_t sw = SWZ128((uint32_t)(r * 128 + cc * 16));
        size_t go = (size_t)(bm + r) * 64 + cc * 8;
        CP_ASYNC16(F_AH + sw, Fhi + go);
        CP_ASYNC16(F_AL + sw, Flo + go);
    }
    #pragma unroll
    for (int it = 0; it < 2; it++) {
        int i = tid + it * 512;
        int r = i >> 3, cc = i & 7;
        uint32_t sw = SWZ128((uint32_t)(r * 128 + cc * 16));
        size_t go = (size_t)r * 64 + cc * 8;
        CP_ASYNC16(W0H + sw, W0h + go);
    }
    CP_COMMIT();
    CP_WAIT0();
    __syncthreads();

    {
        float acc[2][8][4];
        #pragma unroll
        for (int mt = 0; mt < 2; mt++)
            #pragma unroll
            for (int nt = 0; nt < 8; nt++)
                #pragma unroll
                for (int q = 0; q < 4; q++) acc[mt][nt][q] = 0.0f;

        const int arow = wm * 32 + (lane & 15);
        const int brow = wn * 64 + ((lane >> 4) << 3) + (lane & 7);
        const uint32_t acol = (uint32_t)((lane >> 4) << 4);
        const uint32_t bcol = (uint32_t)(((lane >> 3) & 1) << 4);

        #pragma unroll
        for (int ks = 0; ks < 4; ks++) {
            uint32_t ah[2][4], al[2][4], bh[8][2];
            #pragma unroll
            for (int mt = 0; mt < 2; mt++) {
                uint32_t off = SWZ128((uint32_t)((arow + mt * 16) * 128) + ks * 32 + acol);
                LDSM_X4(ah[mt], F_AH + off);
                LDSM_X4(al[mt], F_AL + off);
            }
            #pragma unroll
            for (int p = 0; p < 4; p++) {
                uint32_t off = SWZ128((uint32_t)((brow + p * 16) * 128) + ks * 32 + bcol);
                uint32_t r4[4];
                LDSM_X4(r4, W0H + off);
                bh[2 * p][0] = r4[0]; bh[2 * p][1] = r4[1];
                bh[2 * p + 1][0] = r4[2]; bh[2 * p + 1][1] = r4[3];
            }
            #pragma unroll
            for (int mt = 0; mt < 2; mt++)
                #pragma unroll
                for (int nt = 0; nt < 8; nt++) {
                    mma_f16(acc[mt][nt], ah[mt], bh[nt]);
                    mma_f16(acc[mt][nt], al[mt], bh[nt]);
                }
        }

        #pragma unroll
        for (int nt = 0; nt < 8; nt++) {
            int col = wn * 64 + nt * 8 + 2 * (lane & 3);
            bool act0v = col < 96, act1v = (col + 1) < 96;
            float sc0 = act0v ? __ldg(scAll + col) : 0.f;
            float sh0 = act0v ? __ldg(shAll + col) : 0.f;
            float sc1 = act1v ? __ldg(scAll + col + 1) : 0.f;
            float sh1 = act1v ? __ldg(shAll + col + 1) : 0.f;
            int chunk = col >> 6;
            int ccol = col & 63;
            #pragma unroll
            for (int mt = 0; mt < 2; mt++) {
                int r0 = wm * 32 + mt * 16 + (lane >> 2);
                #pragma unroll
                for (int h = 0; h < 2; h++) {
                    int r = r0 + h * 8;
                    float v0 = act0v ? fmaxf(fmaf(acc[mt][nt][2 * h],     sc0, sh0), 0.f) : 0.f;
                    float v1 = act1v ? fmaxf(fmaf(acc[mt][nt][2 * h + 1], sc1, sh1), 0.f) : 0.f;
                    uint16_t h0, l0, h1, l1;
                    split_fp16(v0, h0, l0);
                    split_fp16(v1, h1, l1);
                    uint32_t off = (uint32_t)chunk * 32768 + SWZ128((uint32_t)(r * 128 + ccol * 2));
                    *(uint32_t*)(smem + (AC0H - sbase) + off) = (uint32_t)h0 | ((uint32_t)h1 << 16);
                    *(uint32_t*)(smem + (AC0L - sbase) + off) = (uint32_t)l0 | ((uint32_t)l1 << 16);
                }
            }
        }
    }
    __syncthreads();

    #pragma unroll
    for (int it = 0; it < 6; it++) {
        int i = tid + it * 512;
        if (i >= 3072) break;
        int chunk = i / 1536;
        int rem = i % 1536;
        int r = rem >> 3, cc = rem & 7;
        uint32_t sw = (uint32_t)chunk * 24576 + SWZ128((uint32_t)(r * 128 + cc * 16));
        size_t go = (size_t)r * 128 + chunk * 64 + cc * 8;
        CP_ASYNC16(W1H + sw, W1h + go);
    }
    CP_COMMIT();
    CP_WAIT0();
    __syncthreads();

    const float* sc1p = scAll + 96;
    const float* sh1p = shAll + 96;
    #pragma unroll 1
    for (int nh = 0; nh < 2; nh++) {
        float acc[2][6][4];
        #pragma unroll
        for (int mt = 0; mt < 2; mt++)
            #pragma unroll
            for (int nt = 0; nt < 6; nt++)
                #pragma unroll
                for (int q = 0; q < 4; q++) acc[mt][nt][q] = 0.0f;

        const int arow = wm * 32 + (lane & 15);
        const int browB = nh * 96 + wn * 48 + ((lane >> 4) << 3) + (lane & 7);
        const uint32_t acol = (uint32_t)((lane >> 4) << 4);
        const uint32_t bcol = (uint32_t)(((lane >> 3) & 1) << 4);

        #pragma unroll
        for (int chunk = 0; chunk < 2; chunk++) {
            #pragma unroll
            for (int ks = 0; ks < 4; ks++) {
                uint32_t ah[2][4], al[2][4], bh[6][2];
                #pragma unroll
                for (int mt = 0; mt < 2; mt++) {
                    uint32_t off = (uint32_t)chunk * 32768 +
                        SWZ128((uint32_t)((arow + mt * 16) * 128) + ks * 32 + acol);
                    LDSM_X4(ah[mt], AC0H + off);
                    LDSM_X4(al[mt], AC0L + off);
                }
                #pragma unroll
                for (int p = 0; p < 3; p++) {
                    uint32_t off = (uint32_t)chunk * 24576 +
                        SWZ128((uint32_t)((browB + p * 16) * 128) + ks * 32 + bcol);
                    uint32_t r4[4];
                    LDSM_X4(r4, W1H + off);
                    bh[2 * p][0] = r4[0]; bh[2 * p][1] = r4[1];
                    bh[2 * p + 1][0] = r4[2]; bh[2 * p + 1][1] = r4[3];
                }
                #pragma unroll
                for (int mt = 0; mt < 2; mt++)
                    #pragma unroll
                    for (int nt = 0; nt < 6; nt++) {
                        mma_f16(acc[mt][nt], ah[mt], bh[nt]);
                        mma_f16(acc[mt][nt], al[mt], bh[nt]);
                    }
            }
        }

        #pragma unroll
        for (int nt = 0; nt < 6; nt++) {
            int col = nh * 96 + wn * 48 + nt * 8 + 2 * (lane & 3);
            float sc0 = __ldg(sc1p + col),     sh0 = __ldg(sh1p + col);
            float sc1 = __ldg(sc1p + col + 1), sh1 = __ldg(sh1p + col + 1);
            #pragma unroll
            for (int mt = 0; mt < 2; mt++) {
                int r0 = bm + wm * 32 + mt * 16 + (lane >> 2);
                #pragma unroll
                for (int h = 0; h < 2; h++) {
                    int r = r0 + h * 8;
                    float v0 = fmaxf(fmaf(acc[mt][nt][2 * h],     sc0, sh0), 0.f);
                    float v1 = fmaxf(fmaf(acc[mt][nt][2 * h + 1], sc1, sh1), 0.f);
                    uint16_t h0, l0, h1, l1;
                    split_fp16(v0, h0, l0);
                    split_fp16(v1, h1, l1);
                    size_t ro = (size_t)r * 192 + col;
                    *(uint32_t*)(Ohi + ro) = (uint32_t)h0 | ((uint32_t)h1 << 16);
                    *(uint32_t*)(Olo + ro) = (uint32_t)l0 | ((uint32_t)l1 << 16);
                }
            }
        }
    }
}

// ===== fp16 2-product HMMA GEMM: 128x128 CTA, 256 thr, 1 CTA/SM (255 regs),
//       3-stage cp.async, explicit fragment double-buffer =====
template<int KPAD, int NACT, int OSTRIDE, int RELU, int FINAL>
__global__ __launch_bounds__(256, 1) void hmma_gemm_kernel(
    const __half* __restrict__ Ahi, const __half* __restrict__ Alo,
    const __half* __restrict__ Bh,
    const float* __restrict__ scale, const float* __restrict__ shift,
    __half* __restrict__ Ohi, __half* __restrict__ Olo,
    float* __restrict__ Ofin)
{
    constexpr int NC = KPAD / 64;
    constexpr int A_BYTES = 128 * 128;          // 16KB per A buffer (hi or lo)
    constexpr int B_BYTES = 128 * 128;          // 16KB
    constexpr int STAGE_BYTES = 2 * A_BYTES + B_BYTES;  // 48KB

    extern __shared__ __align__(1024) char smem[];
    const uint32_t sbase = smem_u32(smem);
    const int tid = threadIdx.x;
    const int wid = tid >> 5;
    const int lane = tid & 31;
    const int wm = wid & 3;
    const int wn = wid >> 2;
    const int bm = blockIdx.y * 128;
    const int bn = blockIdx.x * 128;

    float acc[2][8][4];
    #pragma unroll
    for (int mt = 0; mt < 2; mt++)
        #pragma unroll
        for (int nt = 0; nt < 8; nt++)
            #pragma unroll
            for (int q = 0; q < 4; q++) acc[mt][nt][q] = 0.0f;

    const __half* aHrow = Ahi + (size_t)bm * KPAD;
    const __half* aLrow = Alo + (size_t)bm * KPAD;
    const __half* bHrow = Bh + (size_t)bn * KPAD;

    auto load_stage = [&](int c) {
        const uint32_t so = sbase + (uint32_t)(c % 3) * STAGE_BYTES;
        const int kc = c * 64;
        #pragma unroll
        for (int it = 0; it < 4; it++) {
            int i = tid + it * 256;
            int r = i >> 3, cc = i & 7;
            uint32_t sw = SWZ128((uint32_t)(r * 128 + cc * 16));
            size_t go = (size_t)r * KPAD + kc + cc * 8;
            CP_ASYNC16(so + sw,           aHrow + go);
            CP_ASYNC16(so + A_BYTES + sw, aLrow + go);
        }
        #pragma unroll
        for (int it = 0; it < 4; it++) {
            int i = tid + it * 256;
            int r = i >> 3, cc = i & 7;
            uint32_t sw = SWZ128((uint32_t)(r * 128 + cc * 16));
            size_t go = (size_t)r * KPAD + kc + cc * 8;
            CP_ASYNC16(so + 2 * A_BYTES + sw, bHrow + go);
        }
    };

    // prologue: stages 0 and 1 in flight
    load_stage(0); CP_COMMIT();
    if (1 < NC) load_stage(1);
    CP_COMMIT();

    const int arow = wm * 32 + (lane & 15);
    const int brow = wn * 64 + ((lane >> 4) << 3) + (lane & 7);
    const uint32_t acol = (uint32_t)((lane >> 4) << 4);
    const uint32_t bcol = (uint32_t)(((lane >> 3) & 1) << 4);

    #pragma unroll 1
    for (int c = 0; c < NC; c++) {
        if (c + 2 < NC) load_stage(c + 2);
        CP_COMMIT();
        CP_WAIT2();                 // stage c complete (2 newer groups may be in flight)
        __syncthreads();

        const uint32_t st = sbase + (uint32_t)(c % 3) * STAGE_BYTES;
        const uint32_t sAh = st, sAl = st + A_BYTES;
        const uint32_t sBh = st + 2 * A_BYTES;

        // fragment double-buffer across ks
        uint32_t ah[2][2][4], al[2][2][4], bh[2][8][2];
        auto load_frags = [&](int ks, int buf) {
            #pragma unroll
            for (int mt = 0; mt < 2; mt++) {
                uint32_t off = SWZ128((uint32_t)((arow + mt * 16) * 128) + ks * 32 + acol);
                LDSM_X4(ah[buf][mt], sAh + off);
                LDSM_X4(al[buf][mt], sAl + off);
            }
            #pragma unroll
            for (int p = 0; p < 4; p++) {
                uint32_t off = SWZ128((uint32_t)((brow + p * 16) * 128) + ks * 32 + bcol);
                uint32_t r4[4];
                LDSM_X4(r4, sBh + off);
                bh[buf][2 * p][0] = r4[0]; bh[buf][2 * p][1] = r4[1];
                bh[buf][2 * p + 1][0] = r4[2]; bh[buf][2 * p + 1][1] = r4[3];
            }
        };

        load_frags(0, 0);
        #pragma unroll
        for (int ks = 0; ks < 4; ks++) {
            if (ks < 3) load_frags(ks + 1, (ks + 1) & 1);
            const int bidx = ks & 1;
            #pragma unroll
            for (int mt = 0; mt < 2; mt++)
                #pragma unroll
                for (int nt = 0; nt < 8; nt++) {
                    mma_f16(acc[mt][nt], ah[bidx][mt], bh[bidx][nt]);
                    mma_f16(acc[mt][nt], al[bidx][mt], bh[bidx][nt]);
                }
        }
        __syncthreads();
    }

    if (!FINAL) {
        #pragma unroll
        for (int nt = 0; nt < 8; nt++) {
            int colg = bn + wn * 64 + nt * 8 + 2 * (lane & 3);
            if (colg >= OSTRIDE) continue;
            bool act0 = colg < NACT, act1 = (colg + 1) < NACT;
            float sc0 = act0 ? __ldg(scale + colg) : 0.f;
            float sh0 = act0 ? __ldg(shift + colg) : 0.f;
            float sc1 = act1 ? __ldg(scale + colg + 1) : 0.f;
            float sh1 = act1 ? __ldg(shift + colg + 1) : 0.f;
            #pragma unroll
            for (int mt = 0; mt < 2; mt++) {
                int r0 = bm + wm * 32 + mt * 16 + (lane >> 2);
                #pragma unroll
                for (int h = 0; h < 2; h++) {
                    int r = r0 + h * 8;
                    float v0 = act0 ? fmaf(acc[mt][nt][2 * h],     sc0, sh0) : 0.f;
                    float v1 = act1 ? fmaf(acc[mt][nt][2 * h + 1], sc1, sh1) : 0.f;
                    if (RELU) { v0 = fmaxf(v0, 0.f); v1 = fmaxf(v1, 0.f); }
                    uint16_t h0, l0, h1, l1;
                    split_fp16(v0, h0, l0);
                    split_fp16(v1, h1, l1);
                    size_t ro = (size_t)r * OSTRIDE + colg;
                    *(uint32_t*)(Ohi + ro) = (uint32_t)h0 | ((uint32_t)h1 << 16);
                    *(uint32_t*)(Olo + ro) = (uint32_t)l0 | ((uint32_t)l1 << 16);
                }
            }
        }
    } else {
        // BN then smem transpose, coalesced [b][n][s] store
        float* sf = (float*)smem;            // [128 n][132] floats = 67.6KB < 144KB
        #pragma unroll
        for (int nt = 0; nt < 8; nt++) {
            int coll = wn * 64 + nt * 8 + 2 * (lane & 3);
            int colg = bn + coll;
            float sc0 = __ldg(scale + colg),     sh0 = __ldg(shift + colg);
            float sc1 = __ldg(scale + colg + 1), sh1 = __ldg(shift + colg + 1);
            #pragma unroll
            for (int mt = 0; mt < 2; mt++) {
                int r0 = wm * 32 + mt * 16 + (lane >> 2);
                #pragma unroll
                for (int h = 0; h < 2; h++) {
                    int r = r0 + h * 8;
                    sf[(coll + 0) * 132 + r] = fmaf(acc[mt][nt][2 * h],     sc0, sh0);
                    sf[(coll + 1) * 132 + r] = fmaf(acc[mt][nt][2 * h + 1], sc1, sh1);
                }
            }
        }
        __syncthreads();
        #pragma unroll 1
        for (int i = tid; i < 128 * 128; i += 256) {
            int nl = i >> 7, ml = i & 127;
            int m = bm + ml;
            int b = m / SEGS;
            int s2 = m - b * SEGS;
            Ofin[(size_t)b * 768 * SEGS + (size_t)(bn + nl) * SEGS + s2] = sf[nl * 132 + ml];
        }
    }
}

// ================= launcher =================
extern "C" void kernel_launch(void* const* d_in, const int* in_sizes, int n_in,
                              void* d_out, int out_size)
{
    const float* x      = (const float*)d_in[0];
    const int*   sliced = (const int*)d_in[1];
    PrepArgs pa;
    for (int i = 0; i < 5; i++) {
        int k = 2 + i * 6;
        pa.w[i]  = (const float*)d_in[k + 0];
        pa.bb[i] = (const float*)d_in[k + 1];
        pa.g[i]  = (const float*)d_in[k + 2];
        pa.be[i] = (const float*)d_in[k + 3];
        pa.rm[i] = (const float*)d_in[k + 4];
        pa.rv[i] = (const float*)d_in[k + 5];
    }
    float* out = (float*)d_out;

    void *accP, *h0P, *l0P, *h1P, *l1P, *whP, *scP, *shP;
    cudaGetSymbolAddress(&accP, g_acc);
    cudaGetSymbolAddress(&h0P, g_hi0);
    cudaGetSymbolAddress(&l0P, g_lo0);
    cudaGetSymbolAddress(&h1P, g_hi1);
    cudaGetSymbolAddress(&l1P, g_lo1);
    cudaGetSymbolAddress(&whP, g_wh);
    cudaGetSymbolAddress(&scP, g_scale);
    cudaGetSymbolAddress(&shP, g_shift);
    float* acc = (float*)accP;
    __half* hi0 = (__half*)h0P;
    __half* lo0 = (__half*)l0P;
    __half* hi1 = (__half*)h1P;
    __half* lo1 = (__half*)l1P;
    __half* wh  = (__half*)whP;
    float* sc = (float*)scP;
    float* sh = (float*)shP;

    cudaMemsetAsync(accP, 0, sizeof(float) * 9 * M_ROWS, 0);

    seg_acc_kernel<<<dim3(8, BATCH), 256>>>(x, sliced, out, acc);
    finprep_kernel<<<592, 256>>>(pa, acc, x, hi0, lo0, wh, sc, sh);

    const int WOFF[5] = {0, 8192, 40960, 114688, 409600};
    const int SOFF[5] = {0, 96, 288, 672, 1440};

    const int SMEM_F = 229376;
    cudaFuncSetAttribute(fused01_kernel, cudaFuncAttributeMaxDynamicSharedMemorySize, SMEM_F);
    fused01_kernel<<<dim3(1, 98), 512, SMEM_F>>>(
        hi0, lo0, wh + WOFF[0], wh + WOFF[1], sc, sh, hi1, lo1);

    const int SMEM = 3 * 49152;   // 147456, 3 stages, 1 CTA/SM
    const int MB = M_ROWS / 128;  // 196

    // L2
    cudaFuncSetAttribute(hmma_gemm_kernel<192, 384, 384, 1, 0>,
                         cudaFuncAttributeMaxDynamicSharedMemorySize, SMEM);
    hmma_gemm_kernel<192, 384, 384, 1, 0><<<dim3(3, MB), 256, SMEM>>>(
        hi1, lo1, wh + WOFF[2], sc + SOFF[2], sh + SOFF[2], hi0, lo0, nullptr);

    // L3
    cudaFuncSetAttribute(hmma_gemm_kernel<384, 768, 768, 1, 0>,
                         cudaFuncAttributeMaxDynamicSharedMemorySize, SMEM);
    hmma_gemm_kernel<384, 768, 768, 1, 0><<<dim3(6, MB), 256, SMEM>>>(
        hi0, lo0, wh + WOFF[3], sc + SOFF[3], sh + SOFF[3], hi1, lo1, nullptr);

    // L4 final -> transposed fp32 out
    cudaFuncSetAttribute(hmma_gemm_kernel<768, 768, 768, 0, 1>,
                         cudaFuncAttributeMaxDynamicSharedMemorySize, SMEM);
    hmma_gemm_kernel<768, 768, 768, 0, 1><<<dim3(6, MB), 256, SMEM>>>(
        hi1, lo1, wh + WOFF[4], sc + SOFF[4], sh + SOFF[4], nullptr, nullptr,
        out + OUT_SLICED_ELEMS);
}

// round 15
// speedup vs baseline: 1.0547x; 1.0547x over previous
#include <cuda_runtime.h>
#include <cuda_bf16.h>
#include <cuda_fp16.h>
#include <math.h>
#include <stdint.h>

// ---------------- problem constants ----------------
#define BATCH 128
#define SEGS  196
#define HW    224
#define NPIX  (HW*HW)
#define M_ROWS (BATCH*SEGS)      // 25088 = 128*196
#define BN_EPS 1e-5f
#define OUT_SLICED_ELEMS ((size_t)BATCH*NPIX)

// ================= helpers =================
__device__ __forceinline__ uint32_t smem_u32(const void* p) {
    uint32_t a;
    asm("{ .reg .u64 t; cvta.to.shared.u64 t, %1; cvt.u32.u64 %0, t; }" : "=r"(a) : "l"(p));
    return a;
}
#define SWZ128(off) ((off) ^ (((off) >> 3) & 0x70))

#define CP_ASYNC16(saddr, gptr) \
    asm volatile("cp.async.cg.shared.global [%0], [%1], 16;" :: "r"(saddr), "l"(gptr))
#define CP_COMMIT() asm volatile("cp.async.commit_group;" ::: "memory")
#define CP_WAIT0()  asm volatile("cp.async.wait_group 0;" ::: "memory")
#define CP_WAIT1()  asm volatile("cp.async.wait_group 1;" ::: "memory")

#define LDSM_X4(r, addr) \
    asm volatile("ldmatrix.sync.aligned.m8n8.x4.shared.b16 {%0,%1,%2,%3}, [%4];" \
        : "=r"((r)[0]), "=r"((r)[1]), "=r"((r)[2]), "=r"((r)[3]) : "r"(addr))

__device__ __forceinline__ void mma_f16(float* c, const uint32_t* a, const uint32_t* b) {
    asm volatile(
        "mma.sync.aligned.m16n8k16.row.col.f32.f16.f16.f32 "
        "{%0,%1,%2,%3}, {%4,%5,%6,%7}, {%8,%9}, {%0,%1,%2,%3};"
        : "+f"(c[0]), "+f"(c[1]), "+f"(c[2]), "+f"(c[3])
        : "r"(a[0]), "r"(a[1]), "r"(a[2]), "r"(a[3]), "r"(b[0]), "r"(b[1]));
}

__device__ __forceinline__ void split_fp16(float v, uint16_t& h, uint16_t& l) {
    __half hb = __float2half_rn(v);
    __half lb = __float2half_rn(v - __half2float(hb));
    h = __half_as_ushort(hb);
    l = __half_as_ushort(lb);
}

// ================= scratch (device globals) =================
__device__ unsigned long long g_acc8[(size_t)4 * M_ROWS];   // packed segment accumulators
__device__ __half g_hi0[(size_t)M_ROWS * 768];
__device__ __half g_lo0[(size_t)M_ROWS * 768];
__device__ __half g_hi1[(size_t)M_ROWS * 768];
__device__ __half g_lo1[(size_t)M_ROWS * 768];
__device__ __half g_wh[999424];
__device__ float g_scale[2208];
__device__ float g_shift[2208];

// ================= segment accumulation (packed u64 atomics) =================
// Per segment, 4 u64 accumulators:
//  P0 = count + rowSum<<16 + colSum<<40          (exact integers)
//  P1 = q(v0)  | q(v1)<<32   q(v)=round(v*4096)+32768   (biased fixed point)
//  P2 = s(v0^2)| s(v1^2)<<32 s(u)=round(u*1024)          (unsigned fixed point)
//  P3 = s(v2^2)| q(v2)<<32
__global__ __launch_bounds__(256) void seg_acc_kernel(
    const float* __restrict__ x, const int* __restrict__ sliced,
    float* __restrict__ outSliced, unsigned long long* __restrict__ acc)
{
    __shared__ unsigned long long s[SEGS * 4];
    const int b = blockIdx.y;
    for (int i = threadIdx.x; i < SEGS * 4; i += blockDim.x) s[i] = 0ull;
    __syncthreads();

    const int chunk = NPIX / gridDim.x;
    const int p0 = blockIdx.x * chunk;
    const float* xb = x + (size_t)b * 3 * NPIX;
    const int* sb = sliced + (size_t)b * NPIX;
    float* ob = outSliced + (size_t)b * NPIX;

    for (int p = p0 + threadIdx.x; p < p0 + chunk; p += blockDim.x) {
        int sid = sb[p];
        ob[p] = (float)sid;
        int r = p / HW;
        int c = p - r * HW;
        float v0 = xb[p], v1 = xb[NPIX + p], v2 = xb[2 * NPIX + p];

        unsigned q0 = (unsigned)(__float2int_rn(v0 * 4096.0f) + 32768);
        unsigned q1 = (unsigned)(__float2int_rn(v1 * 4096.0f) + 32768);
        unsigned q2 = (unsigned)(__float2int_rn(v2 * 4096.0f) + 32768);
        unsigned s0 = (unsigned)__float2int_rn(v0 * v0 * 1024.0f);
        unsigned s1 = (unsigned)__float2int_rn(v1 * v1 * 1024.0f);
        unsigned s2 = (unsigned)__float2int_rn(v2 * v2 * 1024.0f);

        unsigned long long* a4 = s + sid * 4;
        atomicAdd(a4 + 0, 1ull + ((unsigned long long)(unsigned)r << 16)
                               + ((unsigned long long)(unsigned)c << 40));
        atomicAdd(a4 + 1, (unsigned long long)q0 | ((unsigned long long)q1 << 32));
        atomicAdd(a4 + 2, (unsigned long long)s0 | ((unsigned long long)s1 << 32));
        atomicAdd(a4 + 3, (unsigned long long)s2 | ((unsigned long long)q2 << 32));
    }
    __syncthreads();
    for (int i = threadIdx.x; i < SEGS * 4; i += blockDim.x) {
        unsigned long long v = s[i];
        if (v != 0ull) {
            int sid = i >> 2, j = i & 3;
            atomicAdd(&acc[((size_t)b * SEGS + sid) * 4 + j], v);
        }
    }
}

// ================= fused finalize + weight/BN prep =================
struct PrepArgs {
    const float* w[5];
    const float* bb[5];
    const float* g[5];
    const float* be[5];
    const float* rm[5];
    const float* rv[5];
};

__global__ __launch_bounds__(256) void finprep_kernel(
    PrepArgs a, const unsigned long long* __restrict__ acc, const float* __restrict__ x,
    __half* __restrict__ fhi, __half* __restrict__ flo,
    __half* __restrict__ wh,
    float* __restrict__ sc, float* __restrict__ sh)
{
    const int NLc[5] = {96, 192, 384, 768, 768};
    const int KLc[5] = {11, 96, 192, 384, 768};
    const int KPc[5] = {64, 128, 192, 384, 768};
    const int WOFFc[6] = {0, 8192, 40960, 114688, 409600, 999424};
    const int SOFFc[6] = {0, 96, 288, 672, 1440, 2208};

    const int stride = gridDim.x * blockDim.x;
    const int tid0 = blockIdx.x * blockDim.x + threadIdx.x;

    for (int idx = tid0; idx < M_ROWS; idx += stride) {
        int b = idx / SEGS;
        unsigned long long P0 = acc[(size_t)idx * 4 + 0];
        unsigned long long P1 = acc[(size_t)idx * 4 + 1];
        unsigned long long P2 = acc[(size_t)idx * 4 + 2];
        unsigned long long P3 = acc[(size_t)idx * 4 + 3];

        unsigned cnt_i = (unsigned)(P0 & 0xFFFFull);
        double rs = (double)((P0 >> 16) & 0xFFFFFFull);
        double cs = (double)(P0 >> 40);
        double bias = (double)cnt_i * 32768.0;
        double v0s = ((double)(P1 & 0xFFFFFFFFull) - bias) * (1.0 / 4096.0);
        double v1s = ((double)(P1 >> 32)           - bias) * (1.0 / 4096.0);
        double v2s = ((double)(P3 >> 32)           - bias) * (1.0 / 4096.0);
        double q0s = (double)(P2 & 0xFFFFFFFFull) * (1.0 / 1024.0);
        double q1s = (double)(P2 >> 32)           * (1.0 / 1024.0);
        double q2s = (double)(P3 & 0xFFFFFFFFull) * (1.0 / 1024.0);

        float cnt = (float)cnt_i;
        float inv = 1.0f / fmaxf(cnt, 1.0f);
        float mrow = (float)rs * inv;
        float mcol = (float)cs * inv;
        float m0 = (float)v0s * inv;
        float m1 = (float)v1s * inv;
        float m2 = (float)v2s * inv;
        float dn = 1.0f / fmaxf(cnt - 1.0f, 1.0f);
        float va0 = ((float)q0s - cnt * m0 * m0) * dn;
        float va1 = ((float)q1s - cnt * m1 * m1) * dn;
        float va2 = ((float)q2s - cnt * m2 * m2) * dn;
        float sd0 = (cnt > 1.0f) ? sqrtf(fmaxf(va0, 0.0f)) : 0.0f;
        float sd1 = (cnt > 1.0f) ? sqrtf(fmaxf(va1, 0.0f)) : 0.0f;
        float sd2 = (cnt > 1.0f) ? sqrtf(fmaxf(va2, 0.0f)) : 0.0f;

        int ri = min(max((int)mrow, 0), HW - 1);
        int ci = min(max((int)mcol, 0), HW - 1);
        const float* xb = x + (size_t)b * 3 * NPIX;
        int pp = ri * HW + ci;
        float mask = (cnt > 0.0f) ? 1.0f : 0.0f;

        float f[11];
        f[0] = mrow * mask; f[1] = mcol * mask;
        f[2] = m0 * mask;   f[3] = m1 * mask;   f[4] = m2 * mask;
        f[5] = sd0 * mask;  f[6] = sd1 * mask;  f[7] = sd2 * mask;
        f[8] = xb[pp] * mask; f[9] = xb[NPIX + pp] * mask; f[10] = xb[2 * NPIX + pp] * mask;

        __half* ph = fhi + (size_t)idx * 64;
        __half* pl = flo + (size_t)idx * 64;
        #pragma unroll
        for (int c = 0; c < 11; c++) {
            __half h = __float2half_rn(f[c]);
            ph[c] = h;
            pl[c] = __float2half_rn(f[c] - __half2float(h));
        }
        for (int c = 11; c < 64; c++) { ph[c] = __float2half_rn(0.f); pl[c] = __float2half_rn(0.f); }
    }

    for (int i = tid0; i < 999424; i += stride) {
        int L = 0;
        while (i >= WOFFc[L + 1]) L++;
        int off = i - WOFFc[L];
        int n = off / KPc[L], k = off - n * KPc[L];
        float v = (n < NLc[L] && k < KLc[L]) ? a.w[L][n * KLc[L] + k] : 0.0f;
        wh[i] = __float2half_rn(v);
    }
    for (int i = tid0; i < 2208; i += stride) {
        int L = 0;
        while (i >= SOFFc[L + 1]) L++;
        int n = i - SOFFc[L];
        float s = a.g[L][n] * rsqrtf(a.rv[L][n] + BN_EPS);
        sc[i] = s;
        sh[i] = (a.bb[L][n] - a.rm[L][n]) * s + a.be[L][n];
    }
}

// ================= fused L0+L1 kernel (fp16 2-product, unchanged) =================
__global__ __launch_bounds__(512, 1) void fused01_kernel(
    const __half* __restrict__ Fhi, const __half* __restrict__ Flo,
    const __half* __restrict__ W0h, const __half* __restrict__ W1h,
    const float* __restrict__ scAll, const float* __restrict__ shAll,
    __half* __restrict__ Ohi, __half* __restrict__ Olo)
{
    extern __shared__ __align__(1024) char smem[];
    const uint32_t sbase = smem_u32(smem);
    const int tid = threadIdx.x;
    const int wid = tid >> 5;
    const int lane = tid & 31;
    const int wm = wid & 7;
    const int wn = wid >> 3;
    const int bm = blockIdx.y * 256;

    const uint32_t F_AH = sbase, F_AL = sbase + 32768;
    const uint32_t W0H = sbase + 65536;
    const uint32_t AC0H = sbase + 98304, AC0L = sbase + 163840;
    const uint32_t W1H = sbase;

    #pragma unroll
    for (int it = 0; it < 4; it++) {
        int i = tid + it * 512;
        int r = i >> 3, cc = i & 7;
        uint32_t sw = SWZ128((uint32_t)(r * 128 + cc * 16));
        size_t go = (size_t)(bm + r) * 64 + cc * 8;
        CP_ASYNC16(F_AH + sw, Fhi + go);
        CP_ASYNC16(F_AL + sw, Flo + go);
    }
    #pragma unroll
    for (int it = 0; it < 2; it++) {
        int i = tid + it * 512;
        int r = i >> 3, cc = i & 7;
        uint32_t sw = SWZ128((uint32_t)(r * 128 + cc * 16));
        size_t go = (size_t)r * 64 + cc * 8;
        CP_ASYNC16(W0H + sw, W0h + go);
    }
    CP_COMMIT();
    CP_WAIT0();
    __syncthreads();

    {
        float acc[2][8][4];
        #pragma unroll
        for (int mt = 0; mt < 2; mt++)
            #pragma unroll
            for (int nt = 0; nt < 8; nt++)
                #pragma unroll
                for (int q = 0; q < 4; q++) acc[mt][nt][q] = 0.0f;

        const int arow = wm * 32 + (lane & 15);
        const int brow = wn * 64 + ((lane >> 4) << 3) + (lane & 7);
        const uint32_t acol = (uint32_t)((lane >> 4) << 4);
        const uint32_t bcol = (uint32_t)(((lane >> 3) & 1) << 4);

        #pragma unroll
        for (int ks = 0; ks < 4; ks++) {
            uint32_t ah[2][4], al[2][4], bh[8][2];
            #pragma unroll
            for (int mt = 0; mt < 2; mt++) {
                uint32_t off = SWZ128((uint32_t)((arow + mt * 16) * 128) + ks * 32 + acol);
                LDSM_X4(ah[mt], F_AH + off);
                LDSM_X4(al[mt], F_AL + off);
            }
            #pragma unroll
            for (int p = 0; p < 4; p++) {
                uint32_t off = SWZ128((uint32_t)((brow + p * 16) * 128) + ks * 32 + bcol);
                uint32_t r4[4];
                LDSM_X4(r4, W0H + off);
                bh[2 * p][0] = r4[0]; bh[2 * p][1] = r4[1];
                bh[2 * p + 1][0] = r4[2]; bh[2 * p + 1][1] = r4[3];
            }
            #pragma unroll
            for (int mt = 0; mt < 2; mt++)
                #pragma unroll
                for (int nt = 0; nt < 8; nt++) {
                    mma_f16(acc[mt][nt], ah[mt], bh[nt]);
                    mma_f16(acc[mt][nt], al[mt], bh[nt]);
                }
        }

        #pragma unroll
        for (int nt = 0; nt < 8; nt++) {
            int col = wn * 64 + nt * 8 + 2 * (lane & 3);
            bool act0v = col < 96, act1v = (col + 1) < 96;
            float sc0 = act0v ? __ldg(scAll + col) : 0.f;
            float sh0 = act0v ? __ldg(shAll + col) : 0.f;
            float sc1 = act1v ? __ldg(scAll + col + 1) : 0.f;
            float sh1 = act1v ? __ldg(shAll + col + 1) : 0.f;
            int chunk = col >> 6;
            int ccol = col & 63;
            #pragma unroll
            for (int mt = 0; mt < 2; mt++) {
                int r0 = wm * 32 + mt * 16 + (lane >> 2);
                #pragma unroll
                for (int h = 0; h < 2; h++) {
                    int r = r0 + h * 8;
                    float v0 = act0v ? fmaxf(fmaf(acc[mt][nt][2 * h],     sc0, sh0), 0.f) : 0.f;
                    float v1 = act1v ? fmaxf(fmaf(acc[mt][nt][2 * h + 1], sc1, sh1), 0.f) : 0.f;
                    uint16_t h0, l0, h1, l1;
                    split_fp16(v0, h0, l0);
                    split_fp16(v1, h1, l1);
                    uint32_t off = (uint32_t)chunk * 32768 + SWZ128((uint32_t)(r * 128 + ccol * 2));
                    *(uint32_t*)(smem + (AC0H - sbase) + off) = (uint32_t)h0 | ((uint32_t)h1 << 16);
                    *(uint32_t*)(smem + (AC0L - sbase) + off) = (uint32_t)l0 | ((uint32_t)l1 << 16);
                }
            }
        }
    }
    __syncthreads();

    #pragma unroll
    for (int it = 0; it < 6; it++) {
        int i = tid + it * 512;
        if (i >= 3072) break;
        int chunk = i / 1536;
        int rem = i % 1536;
        int r = rem >> 3, cc = rem & 7;
        uint32_t sw = (uint32_t)chunk * 24576 + SWZ128((uint32_t)(r * 128 + cc * 16));
        size_t go = (size_t)r * 128 + chunk * 64 + cc * 8;
        CP_ASYNC16(W1H + sw, W1h + go);
    }
    CP_COMMIT();
    CP_WAIT0();
    __syncthreads();

    const float* sc1p = scAll + 96;
    const float* sh1p = shAll + 96;
    #pragma unroll 1
    for (int nh = 0; nh < 2; nh++) {
        float acc[2][6][4];
        #pragma unroll
        for (int mt = 0; mt < 2; mt++)
            #pragma unroll
            for (int nt = 0; nt < 6; nt++)
                #pragma unroll
                for (int q = 0; q < 4; q++) acc[mt][nt][q] = 0.0f;

        const int arow = wm * 32 + (lane & 15);
        const int browB = nh * 96 + wn * 48 + ((lane >> 4) << 3) + (lane & 7);
        const uint32_t acol = (uint32_t)((lane >> 4) << 4);
        const uint32_t bcol = (uint32_t)(((lane >> 3) & 1) << 4);

        #pragma unroll
        for (int chunk = 0; chunk < 2; chunk++) {
            #pragma unroll
            for (int ks = 0; ks < 4; ks++) {
                uint32_t ah[2][4], al[2][4], bh[6][2];
                #pragma unroll
                for (int mt = 0; mt < 2; mt++) {
                    uint32_t off = (uint32_t)chunk * 32768 +
                        SWZ128((uint32_t)((arow + mt * 16) * 128) + ks * 32 + acol);
                    LDSM_X4(ah[mt], AC0H + off);
                    LDSM_X4(al[mt], AC0L + off);
                }
                #pragma unroll
                for (int p = 0; p < 3; p++) {
                    uint32_t off = (uint32_t)chunk * 24576 +
                        SWZ128((uint32_t)((browB + p * 16) * 128) + ks * 32 + bcol);
                    uint32_t r4[4];
                    LDSM_X4(r4, W1H + off);
                    bh[2 * p][0] = r4[0]; bh[2 * p][1] = r4[1];
                    bh[2 * p + 1][0] = r4[2]; bh[2 * p + 1][1] = r4[3];
                }
                #pragma unroll
                for (int mt = 0; mt < 2; mt++)
                    #pragma unroll
                    for (int nt = 0; nt < 6; nt++) {
                        mma_f16(acc[mt][nt], ah[mt], bh[nt]);
                        mma_f16(acc[mt][nt], al[mt], bh[nt]);
                    }
            }
        }

        #pragma unroll
        for (int nt = 0; nt < 6; nt++) {
            int col = nh * 96 + wn * 48 + nt * 8 + 2 * (lane & 3);
            float sc0 = __ldg(sc1p + col),     sh0 = __ldg(sh1p + col);
            float sc1 = __ldg(sc1p + col + 1), sh1 = __ldg(sh1p + col + 1);
            #pragma unroll
            for (int mt = 0; mt < 2; mt++) {
                int r0 = bm + wm * 32 + mt * 16 + (lane >> 2);
                #pragma unroll
                for (int h = 0; h < 2; h++) {
                    int r = r0 + h * 8;
                    float v0 = fmaxf(fmaf(acc[mt][nt][2 * h],     sc0, sh0), 0.f);
                    float v1 = fmaxf(fmaf(acc[mt][nt][2 * h + 1], sc1, sh1), 0.f);
                    uint16_t h0, l0, h1, l1;
                    split_fp16(v0, h0, l0);
                    split_fp16(v1, h1, l1);
                    size_t ro = (size_t)r * 192 + col;
                    *(uint32_t*)(Ohi + ro) = (uint32_t)h0 | ((uint32_t)h1 << 16);
                    *(uint32_t*)(Olo + ro) = (uint32_t)l0 | ((uint32_t)l1 << 16);
                }
            }
        }
    }
}

// ===== fp16 2-product HMMA GEMM: 128x128 CTA tile, 8 warps, 2 CTAs/SM, K64 2-stage (R13 proven) =====
template<int KPAD, int NACT, int OSTRIDE, int RELU, int FINAL>
__global__ __launch_bounds__(256, 2) void hmma_gemm_kernel(
    const __half* __restrict__ Ahi, const __half* __restrict__ Alo,
    const __half* __restrict__ Bh,
    const float* __restrict__ scale, const float* __restrict__ shift,
    __half* __restrict__ Ohi, __half* __restrict__ Olo,
    float* __restrict__ Ofin)
{
    constexpr int NC = KPAD / 64;
    constexpr int A_BYTES = 128 * 128;
    constexpr int B_BYTES = 128 * 128;
    constexpr int STAGE_BYTES = 2 * A_BYTES + B_BYTES;  // 48KB

    extern __shared__ __align__(1024) char smem[];
    const uint32_t sbase = smem_u32(smem);
    const int tid = threadIdx.x;
    const int wid = tid >> 5;
    const int lane = tid & 31;
    const int wm = wid & 3;
    const int wn = wid >> 2;
    const int bm = blockIdx.y * 128;
    const int bn = blockIdx.x * 128;

    float acc[2][8][4];
    #pragma unroll
    for (int mt = 0; mt < 2; mt++)
        #pragma unroll
        for (int nt = 0; nt < 8; nt++)
            #pragma unroll
            for (int q = 0; q < 4; q++) acc[mt][nt][q] = 0.0f;

    const __half* aHrow = Ahi + (size_t)bm * KPAD;
    const __half* aLrow = Alo + (size_t)bm * KPAD;
    const __half* bHrow = Bh + (size_t)bn * KPAD;

    auto load_stage = [&](int c) {
        const uint32_t so = sbase + (uint32_t)(c & 1) * STAGE_BYTES;
        const int kc = c * 64;
        #pragma unroll
        for (int it = 0; it < 4; it++) {
            int i = tid + it * 256;
            int r = i >> 3, cc = i & 7;
            uint32_t sw = SWZ128((uint32_t)(r * 128 + cc * 16));
            size_t go = (size_t)r * KPAD + kc + cc * 8;
            CP_ASYNC16(so + sw,           aHrow + go);
            CP_ASYNC16(so + A_BYTES + sw, aLrow + go);
        }
        #pragma unroll
        for (int it = 0; it < 4; it++) {
            int i = tid + it * 256;
            int r = i >> 3, cc = i & 7;
            uint32_t sw = SWZ128((uint32_t)(r * 128 + cc * 16));
            size_t go = (size_t)r * KPAD + kc + cc * 8;
            CP_ASYNC16(so + 2 * A_BYTES + sw, bHrow + go);
        }
    };

    load_stage(0);
    CP_COMMIT();

    const int arow = wm * 32 + (lane & 15);
    const int brow = wn * 64 + ((lane >> 4) << 3) + (lane & 7);
    const uint32_t acol = (uint32_t)((lane >> 4) << 4);
    const uint32_t bcol = (uint32_t)(((lane >> 3) & 1) << 4);

    #pragma unroll 1
    for (int c = 0; c < NC; c++) {
        if (c + 1 < NC) { load_stage(c + 1); CP_COMMIT(); CP_WAIT1(); }
        else            { CP_WAIT0(); }
        __syncthreads();

        const uint32_t st = sbase + (uint32_t)(c & 1) * STAGE_BYTES;
        const uint32_t sAh = st, sAl = st + A_BYTES;
        const uint32_t sBh = st + 2 * A_BYTES;

        #pragma unroll
        for (int ks = 0; ks < 4; ks++) {
            uint32_t ah[2][4], al[2][4], bh[8][2];
            #pragma unroll
            for (int mt = 0; mt < 2; mt++) {
                uint32_t off = SWZ128((uint32_t)((arow + mt * 16) * 128) + ks * 32 + acol);
                LDSM_X4(ah[mt], sAh + off);
                LDSM_X4(al[mt], sAl + off);
            }
            #pragma unroll
            for (int p = 0; p < 4; p++) {
                uint32_t off = SWZ128((uint32_t)((brow + p * 16) * 128) + ks * 32 + bcol);
                uint32_t r4[4];
                LDSM_X4(r4, sBh + off);
                bh[2 * p][0] = r4[0]; bh[2 * p][1] = r4[1];
                bh[2 * p + 1][0] = r4[2]; bh[2 * p + 1][1] = r4[3];
            }
            #pragma unroll
            for (int mt = 0; mt < 2; mt++)
                #pragma unroll
                for (int nt = 0; nt < 8; nt++) {
                    mma_f16(acc[mt][nt], ah[mt], bh[nt]);
                    mma_f16(acc[mt][nt], al[mt], bh[nt]);
                }
        }
        __syncthreads();
    }

    if (!FINAL) {
        #pragma unroll
        for (int nt = 0; nt < 8; nt++) {
            int colg = bn + wn * 64 + nt * 8 + 2 * (lane & 3);
            if (colg >= OSTRIDE) continue;
            bool act0 = colg < NACT, act1 = (colg + 1) < NACT;
            float sc0 = act0 ? __ldg(scale + colg) : 0.f;
            float sh0 = act0 ? __ldg(shift + colg) : 0.f;
            float sc1 = act1 ? __ldg(scale + colg + 1) : 0.f;
            float sh1 = act1 ? __ldg(shift + colg + 1) : 0.f;
            #pragma unroll
            for (int mt = 0; mt < 2; mt++) {
                int r0 = bm + wm * 32 + mt * 16 + (lane >> 2);
                #pragma unroll
                for (int h = 0; h < 2; h++) {
                    int r = r0 + h * 8;
                    float v0 = act0 ? fmaf(acc[mt][nt][2 * h],     sc0, sh0) : 0.f;
                    float v1 = act1 ? fmaf(acc[mt][nt][2 * h + 1], sc1, sh1) : 0.f;
                    if (RELU) { v0 = fmaxf(v0, 0.f); v1 = fmaxf(v1, 0.f); }
                    uint16_t h0, l0, h1, l1;
                    split_fp16(v0, h0, l0);
                    split_fp16(v1, h1, l1);
                    size_t ro = (size_t)r * OSTRIDE + colg;
                    *(uint32_t*)(Ohi + ro) = (uint32_t)h0 | ((uint32_t)h1 << 16);
                    *(uint32_t*)(Olo + ro) = (uint32_t)l0 | ((uint32_t)l1 << 16);
                }
            }
        }
    } else {
        float* sf = (float*)smem;            // [128 n][132] floats = 67.6KB < 96KB
        #pragma unroll
        for (int nt = 0; nt < 8; nt++) {
            int coll = wn * 64 + nt * 8 + 2 * (lane & 3);
            int colg = bn + coll;
            float sc0 = __ldg(scale + colg),     sh0 = __ldg(shift + colg);
            float sc1 = __ldg(scale + colg + 1), sh1 = __ldg(shift + colg + 1);
            #pragma unroll
            for (int mt = 0; mt < 2; mt++) {
                int r0 = wm * 32 + mt * 16 + (lane >> 2);
                #pragma unroll
                for (int h = 0; h < 2; h++) {
                    int r = r0 + h * 8;
                    sf[(coll + 0) * 132 + r] = fmaf(acc[mt][nt][2 * h],     sc0, sh0);
                    sf[(coll + 1) * 132 + r] = fmaf(acc[mt][nt][2 * h + 1], sc1, sh1);
                }
            }
        }
        __syncthreads();
        #pragma unroll 1
        for (int i = tid; i < 128 * 128; i += 256) {
            int nl = i >> 7, ml = i & 127;
            int m = bm + ml;
            int b = m / SEGS;
            int s2 = m - b * SEGS;
            Ofin[(size_t)b * 768 * SEGS + (size_t)(bn + nl) * SEGS + s2] = sf[nl * 132 + ml];
        }
    }
}

// ================= launcher =================
extern "C" void kernel_launch(void* const* d_in, const int* in_sizes, int n_in,
                              void* d_out, int out_size)
{
    const float* x      = (const float*)d_in[0];
    const int*   sliced = (const int*)d_in[1];
    PrepArgs pa;
    for (int i = 0; i < 5; i++) {
        int k = 2 + i * 6;
        pa.w[i]  = (const float*)d_in[k + 0];
        pa.bb[i] = (const float*)d_in[k + 1];
        pa.g[i]  = (const float*)d_in[k + 2];
        pa.be[i] = (const float*)d_in[k + 3];
        pa.rm[i] = (const float*)d_in[k + 4];
        pa.rv[i] = (const float*)d_in[k + 5];
    }
    float* out = (float*)d_out;

    void *accP, *h0P, *l0P, *h1P, *l1P, *whP, *scP, *shP;
    cudaGetSymbolAddress(&accP, g_acc8);
    cudaGetSymbolAddress(&h0P, g_hi0);
    cudaGetSymbolAddress(&l0P, g_lo0);
    cudaGetSymbolAddress(&h1P, g_hi1);
    cudaGetSymbolAddress(&l1P, g_lo1);
    cudaGetSymbolAddress(&whP, g_wh);
    cudaGetSymbolAddress(&scP, g_scale);
    cudaGetSymbolAddress(&shP, g_shift);
    unsigned long long* acc = (unsigned long long*)accP;
    __half* hi0 = (__half*)h0P;
    __half* lo0 = (__half*)l0P;
    __half* hi1 = (__half*)h1P;
    __half* lo1 = (__half*)l1P;
    __half* wh  = (__half*)whP;
    float* sc = (float*)scP;
    float* sh = (float*)shP;

    cudaMemsetAsync(accP, 0, sizeof(unsigned long long) * 4 * M_ROWS, 0);

    seg_acc_kernel<<<dim3(8, BATCH), 256>>>(x, sliced, out, acc);
    finprep_kernel<<<592, 256>>>(pa, acc, x, hi0, lo0, wh, sc, sh);

    const int WOFF[5] = {0, 8192, 40960, 114688, 409600};
    const int SOFF[5] = {0, 96, 288, 672, 1440};

    const int SMEM_F = 229376;
    cudaFuncSetAttribute(fused01_kernel, cudaFuncAttributeMaxDynamicSharedMemorySize, SMEM_F);
    fused01_kernel<<<dim3(1, 98), 512, SMEM_F>>>(
        hi0, lo0, wh + WOFF[0], wh + WOFF[1], sc, sh, hi1, lo1);

    const int SMEM = 2 * 49152;   // 98304 -> 2 CTAs/SM
    const int MB = M_ROWS / 128;  // 196

    // L2
    cudaFuncSetAttribute(hmma_gemm_kernel<192, 384, 384, 1, 0>,
                         cudaFuncAttributeMaxDynamicSharedMemorySize, SMEM);
    hmma_gemm_kernel<192, 384, 384, 1, 0><<<dim3(3, MB), 256, SMEM>>>(
        hi1, lo1, wh + WOFF[2], sc + SOFF[2], sh + SOFF[2], hi0, lo0, nullptr);

    // L3
    cudaFuncSetAttribute(hmma_gemm_kernel<384, 768, 768, 1, 0>,
                         cudaFuncAttributeMaxDynamicSharedMemorySize, SMEM);
    hmma_gemm_kernel<384, 768, 768, 1, 0><<<dim3(6, MB), 256, SMEM>>>(
        hi0, lo0, wh + WOFF[3], sc + SOFF[3], sh + SOFF[3], hi1, lo1, nullptr);

    // L4 final -> transposed fp32 out
    cudaFuncSetAttribute(hmma_gemm_kernel<768, 768, 768, 0, 1>,
                         cudaFuncAttributeMaxDynamicSharedMemorySize, SMEM);
    hmma_gemm_kernel<768, 768, 768, 0, 1><<<dim3(6, MB), 256, SMEM>>>(
        hi1, lo1, wh + WOFF[4], sc + SOFF[4], sh + SOFF[4], nullptr, nullptr,
        out + OUT_SLICED_ELEMS);
}

// round 16
// speedup vs baseline: 1.1060x; 1.0486x over previous
#include <cuda_runtime.h>
#include <cuda_bf16.h>
#include <cuda_fp16.h>
#include <math.h>
#include <stdint.h>

// ---------------- problem constants ----------------
#define BATCH 128
#define SEGS  196
#define HW    224
#define NPIX  (HW*HW)
#define M_ROWS (BATCH*SEGS)      // 25088 = 128*196
#define BN_EPS 1e-5f
#define OUT_SLICED_ELEMS ((size_t)BATCH*NPIX)

// ================= helpers =================
__device__ __forceinline__ uint32_t smem_u32(const void* p) {
    uint32_t a;
    asm("{ .reg .u64 t; cvta.to.shared.u64 t, %1; cvt.u32.u64 %0, t; }" : "=r"(a) : "l"(p));
    return a;
}
#define SWZ128(off) ((off) ^ (((off) >> 3) & 0x70))

#define CP_ASYNC16(saddr, gptr) \
    asm volatile("cp.async.cg.shared.global [%0], [%1], 16;" :: "r"(saddr), "l"(gptr))
#define CP_COMMIT() asm volatile("cp.async.commit_group;" ::: "memory")
#define CP_WAIT0()  asm volatile("cp.async.wait_group 0;" ::: "memory")
#define CP_WAIT1()  asm volatile("cp.async.wait_group 1;" ::: "memory")

#define LDSM_X4(r, addr) \
    asm volatile("ldmatrix.sync.aligned.m8n8.x4.shared.b16 {%0,%1,%2,%3}, [%4];" \
        : "=r"((r)[0]), "=r"((r)[1]), "=r"((r)[2]), "=r"((r)[3]) : "r"(addr))

__device__ __forceinline__ void mma_f16(float* c, const uint32_t* a, const uint32_t* b) {
    asm volatile(
        "mma.sync.aligned.m16n8k16.row.col.f32.f16.f16.f32 "
        "{%0,%1,%2,%3}, {%4,%5,%6,%7}, {%8,%9}, {%0,%1,%2,%3};"
        : "+f"(c[0]), "+f"(c[1]), "+f"(c[2]), "+f"(c[3])
        : "r"(a[0]), "r"(a[1]), "r"(a[2]), "r"(a[3]), "r"(b[0]), "r"(b[1]));
}

__device__ __forceinline__ void split_fp16(float v, uint16_t& h, uint16_t& l) {
    __half hb = __float2half_rn(v);
    __half lb = __float2half_rn(v - __half2float(hb));
    h = __half_as_ushort(hb);
    l = __half_as_ushort(lb);
}

// ================= scratch (device globals) =================
__device__ float g_acc[9 * M_ROWS];
__device__ __half g_hi0[(size_t)M_ROWS * 768];
__device__ __half g_lo0[(size_t)M_ROWS * 768];
__device__ __half g_hi1[(size_t)M_ROWS * 768];
__device__ __half g_lo1[(size_t)M_ROWS * 768];
__device__ __half g_wh[999424];
__device__ float g_scale[2208];
__device__ float g_shift[2208];

// ================= segment accumulation: run-length local accumulation =================
// 448 threads, grid (14, BATCH). Each thread: 8 contiguous pixels.
// Superpixel runs mean ~1.4 flushes per 8 pixels instead of 8.
#define SEG_THREADS 448
#define PXT 8
__global__ __launch_bounds__(SEG_THREADS) void seg_acc_kernel(
    const float* __restrict__ x, const int* __restrict__ sliced,
    float* __restrict__ outSliced, float* __restrict__ acc)
{
    __shared__ float s[SEGS * 9];
    const int b = blockIdx.y;
    for (int i = threadIdx.x; i < SEGS * 9; i += SEG_THREADS) s[i] = 0.0f;
    __syncthreads();

    const int base = (blockIdx.x * SEG_THREADS + threadIdx.x) * PXT;
    const float* xb = x + (size_t)b * 3 * NPIX;
    const int* sb = sliced + (size_t)b * NPIX;
    float* ob = outSliced + (size_t)b * NPIX;

    // vector loads: 2x int4 sids, 2x float4 per channel
    int4 si0 = *(const int4*)(sb + base);
    int4 si1 = *(const int4*)(sb + base + 4);
    float4 c0a = *(const float4*)(xb + base);
    float4 c0b = *(const float4*)(xb + base + 4);
    float4 c1a = *(const float4*)(xb + NPIX + base);
    float4 c1b = *(const float4*)(xb + NPIX + base + 4);
    float4 c2a = *(const float4*)(xb + 2 * NPIX + base);
    float4 c2b = *(const float4*)(xb + 2 * NPIX + base + 4);

    int sid8[PXT] = {si0.x, si0.y, si0.z, si0.w, si1.x, si1.y, si1.z, si1.w};
    float v0a[PXT] = {c0a.x, c0a.y, c0a.z, c0a.w, c0b.x, c0b.y, c0b.z, c0b.w};
    float v1a[PXT] = {c1a.x, c1a.y, c1a.z, c1a.w, c1b.x, c1b.y, c1b.z, c1b.w};
    float v2a[PXT] = {c2a.x, c2a.y, c2a.z, c2a.w, c2b.x, c2b.y, c2b.z, c2b.w};

    // write float-converted sliced (coalesced float4 stores)
    {
        float4 o0 = make_float4((float)sid8[0], (float)sid8[1], (float)sid8[2], (float)sid8[3]);
        float4 o1 = make_float4((float)sid8[4], (float)sid8[5], (float)sid8[6], (float)sid8[7]);
        *(float4*)(ob + base) = o0;
        *(float4*)(ob + base + 4) = o1;
    }

    float l0 = 0, l1 = 0, l2 = 0, l3 = 0, l4 = 0, l5 = 0, l6 = 0, l7 = 0, l8 = 0;
    int cur = sid8[0];

    #pragma unroll
    for (int j = 0; j < PXT; j++) {
        int sid = sid8[j];
        if (sid != cur) {
            float* a9 = s + cur * 9;
            atomicAdd(a9 + 0, l0); atomicAdd(a9 + 1, l1); atomicAdd(a9 + 2, l2);
            atomicAdd(a9 + 3, l3); atomicAdd(a9 + 4, l4); atomicAdd(a9 + 5, l5);
            atomicAdd(a9 + 6, l6); atomicAdd(a9 + 7, l7); atomicAdd(a9 + 8, l8);
            l0 = l1 = l2 = l3 = l4 = l5 = l6 = l7 = l8 = 0.0f;
            cur = sid;
        }
        int p = base + j;
        int r = p / HW;
        int c = p - r * HW;
        float v0 = v0a[j], v1 = v1a[j], v2 = v2a[j];
        l0 += 1.0f; l1 += (float)r; l2 += (float)c;
        l3 += v0; l4 += v1; l5 += v2;
        l6 += v0 * v0; l7 += v1 * v1; l8 += v2 * v2;
    }
    {
        float* a9 = s + cur * 9;
        atomicAdd(a9 + 0, l0); atomicAdd(a9 + 1, l1); atomicAdd(a9 + 2, l2);
        atomicAdd(a9 + 3, l3); atomicAdd(a9 + 4, l4); atomicAdd(a9 + 5, l5);
        atomicAdd(a9 + 6, l6); atomicAdd(a9 + 7, l7); atomicAdd(a9 + 8, l8);
    }
    __syncthreads();

    for (int i = threadIdx.x; i < SEGS * 9; i += SEG_THREADS) {
        float v = s[i];
        if (v != 0.0f) {
            int sid = i / 9, f = i - sid * 9;
            atomicAdd(&acc[(size_t)f * M_ROWS + b * SEGS + sid], v);
        }
    }
}

// ================= fused finalize + weight/BN prep (R13 float version) =================
struct PrepArgs {
    const float* w[5];
    const float* bb[5];
    const float* g[5];
    const float* be[5];
    const float* rm[5];
    const float* rv[5];
};

__global__ __launch_bounds__(256) void finprep_kernel(
    PrepArgs a, const float* __restrict__ acc, const float* __restrict__ x,
    __half* __restrict__ fhi, __half* __restrict__ flo,
    __half* __restrict__ wh,
    float* __restrict__ sc, float* __restrict__ sh)
{
    const int NLc[5] = {96, 192, 384, 768, 768};
    const int KLc[5] = {11, 96, 192, 384, 768};
    const int KPc[5] = {64, 128, 192, 384, 768};
    const int WOFFc[6] = {0, 8192, 40960, 114688, 409600, 999424};
    const int SOFFc[6] = {0, 96, 288, 672, 1440, 2208};

    const int stride = gridDim.x * blockDim.x;
    const int tid0 = blockIdx.x * blockDim.x + threadIdx.x;

    for (int idx = tid0; idx < M_ROWS; idx += stride) {
        int b = idx / SEGS;
        float cnt  = acc[idx];
        float inv  = 1.0f / fmaxf(cnt, 1.0f);
        float mrow = acc[(size_t)1 * M_ROWS + idx] * inv;
        float mcol = acc[(size_t)2 * M_ROWS + idx] * inv;
        float m0 = acc[(size_t)3 * M_ROWS + idx] * inv;
        float m1 = acc[(size_t)4 * M_ROWS + idx] * inv;
        float m2 = acc[(size_t)5 * M_ROWS + idx] * inv;
        float dn = 1.0f / fmaxf(cnt - 1.0f, 1.0f);
        float v0 = (acc[(size_t)6 * M_ROWS + idx] - cnt * m0 * m0) * dn;
        float v1 = (acc[(size_t)7 * M_ROWS + idx] - cnt * m1 * m1) * dn;
        float v2 = (acc[(size_t)8 * M_ROWS + idx] - cnt * m2 * m2) * dn;
        float sd0 = (cnt > 1.0f) ? sqrtf(fmaxf(v0, 0.0f)) : 0.0f;
        float sd1 = (cnt > 1.0f) ? sqrtf(fmaxf(v1, 0.0f)) : 0.0f;
        float sd2 = (cnt > 1.0f) ? sqrtf(fmaxf(v2, 0.0f)) : 0.0f;

        int ri = min(max((int)mrow, 0), HW - 1);
        int ci = min(max((int)mcol, 0), HW - 1);
        const float* xb = x + (size_t)b * 3 * NPIX;
        int pp = ri * HW + ci;
        float mask = (cnt > 0.0f) ? 1.0f : 0.0f;

        float f[11];
        f[0] = mrow * mask; f[1] = mcol * mask;
        f[2] = m0 * mask;   f[3] = m1 * mask;   f[4] = m2 * mask;
        f[5] = sd0 * mask;  f[6] = sd1 * mask;  f[7] = sd2 * mask;
        f[8] = xb[pp] * mask; f[9] = xb[NPIX + pp] * mask; f[10] = xb[2 * NPIX + pp] * mask;

        __half* ph = fhi + (size_t)idx * 64;
        __half* pl = flo + (size_t)idx * 64;
        #pragma unroll
        for (int c = 0; c < 11; c++) {
            __half h = __float2half_rn(f[c]);
            ph[c] = h;
            pl[c] = __float2half_rn(f[c] - __half2float(h));
        }
        for (int c = 11; c < 64; c++) { ph[c] = __float2half_rn(0.f); pl[c] = __float2half_rn(0.f); }
    }

    for (int i = tid0; i < 999424; i += stride) {
        int L = 0;
        while (i >= WOFFc[L + 1]) L++;
        int off = i - WOFFc[L];
        int n = off / KPc[L], k = off - n * KPc[L];
        float v = (n < NLc[L] && k < KLc[L]) ? a.w[L][n * KLc[L] + k] : 0.0f;
        wh[i] = __float2half_rn(v);
    }
    for (int i = tid0; i < 2208; i += stride) {
        int L = 0;
        while (i >= SOFFc[L + 1]) L++;
        int n = i - SOFFc[L];
        float s = a.g[L][n] * rsqrtf(a.rv[L][n] + BN_EPS);
        sc[i] = s;
        sh[i] = (a.bb[L][n] - a.rm[L][n]) * s + a.be[L][n];
    }
}

// ================= fused L0+L1 kernel (fp16 2-product, unchanged) =================
__global__ __launch_bounds__(512, 1) void fused01_kernel(
    const __half* __restrict__ Fhi, const __half* __restrict__ Flo,
    const __half* __restrict__ W0h, const __half* __restrict__ W1h,
    const float* __restrict__ scAll, const float* __restrict__ shAll,
    __half* __restrict__ Ohi, __half* __restrict__ Olo)
{
    extern __shared__ __align__(1024) char smem[];
    const uint32_t sbase = smem_u32(smem);
    const int tid = threadIdx.x;
    const int wid = tid >> 5;
    const int lane = tid & 31;
    const int wm = wid & 7;
    const int wn = wid >> 3;
    const int bm = blockIdx.y * 256;

    const uint32_t F_AH = sbase, F_AL = sbase + 32768;
    const uint32_t W0H = sbase + 65536;
    const uint32_t AC0H = sbase + 98304, AC0L = sbase + 163840;
    const uint32_t W1H = sbase;

    #pragma unroll
    for (int it = 0; it < 4; it++) {
        int i = tid + it * 512;
        int r = i >> 3, cc = i & 7;
        uint32_t sw = SWZ128((uint32_t)(r * 128 + cc * 16));
        size_t go = (size_t)(bm + r) * 64 + cc * 8;
        CP_ASYNC16(F_AH + sw, Fhi + go);
        CP_ASYNC16(F_AL + sw, Flo + go);
    }
    #pragma unroll
    for (int it = 0; it < 2; it++) {
        int i = tid + it * 512;
        int r = i >> 3, cc = i & 7;
        uint32_t sw = SWZ128((uint32_t)(r * 128 + cc * 16));
        size_t go = (size_t)r * 64 + cc * 8;
        CP_ASYNC16(W0H + sw, W0h + go);
    }
    CP_COMMIT();
    CP_WAIT0();
    __syncthreads();

    {
        float acc[2][8][4];
        #pragma unroll
        for (int mt = 0; mt < 2; mt++)
            #pragma unroll
            for (int nt = 0; nt < 8; nt++)
                #pragma unroll
                for (int q = 0; q < 4; q++) acc[mt][nt][q] = 0.0f;

        const int arow = wm * 32 + (lane & 15);
        const int brow = wn * 64 + ((lane >> 4) << 3) + (lane & 7);
        const uint32_t acol = (uint32_t)((lane >> 4) << 4);
        const uint32_t bcol = (uint32_t)(((lane >> 3) & 1) << 4);

        #pragma unroll
        for (int ks = 0; ks < 4; ks++) {
            uint32_t ah[2][4], al[2][4], bh[8][2];
            #pragma unroll
            for (int mt = 0; mt < 2; mt++) {
                uint32_t off = SWZ128((uint32_t)((arow + mt * 16) * 128) + ks * 32 + acol);
                LDSM_X4(ah[mt], F_AH + off);
                LDSM_X4(al[mt], F_AL + off);
            }
            #pragma unroll
            for (int p = 0; p < 4; p++) {
                uint32_t off = SWZ128((uint32_t)((brow + p * 16) * 128) + ks * 32 + bcol);
                uint32_t r4[4];
                LDSM_X4(r4, W0H + off);
                bh[2 * p][0] = r4[0]; bh[2 * p][1] = r4[1];
                bh[2 * p + 1][0] = r4[2]; bh[2 * p + 1][1] = r4[3];
            }
            #pragma unroll
            for (int mt = 0; mt < 2; mt++)
                #pragma unroll
                for (int nt = 0; nt < 8; nt++) {
                    mma_f16(acc[mt][nt], ah[mt], bh[nt]);
                    mma_f16(acc[mt][nt], al[mt], bh[nt]);
                }
        }

        #pragma unroll
        for (int nt = 0; nt < 8; nt++) {
            int col = wn * 64 + nt * 8 + 2 * (lane & 3);
            bool act0v = col < 96, act1v = (col + 1) < 96;
            float sc0 = act0v ? __ldg(scAll + col) : 0.f;
            float sh0 = act0v ? __ldg(shAll + col) : 0.f;
            float sc1 = act1v ? __ldg(scAll + col + 1) : 0.f;
            float sh1 = act1v ? __ldg(shAll + col + 1) : 0.f;
            int chunk = col >> 6;
            int ccol = col & 63;
            #pragma unroll
            for (int mt = 0; mt < 2; mt++) {
                int r0 = wm * 32 + mt * 16 + (lane >> 2);
                #pragma unroll
                for (int h = 0; h < 2; h++) {
                    int r = r0 + h * 8;
                    float v0 = act0v ? fmaxf(fmaf(acc[mt][nt][2 * h],     sc0, sh0), 0.f) : 0.f;
                    float v1 = act1v ? fmaxf(fmaf(acc[mt][nt][2 * h + 1], sc1, sh1), 0.f) : 0.f;
                    uint16_t h0, l0, h1, l1;
                    split_fp16(v0, h0, l0);
                    split_fp16(v1, h1, l1);
                    uint32_t off = (uint32_t)chunk * 32768 + SWZ128((uint32_t)(r * 128 + ccol * 2));
                    *(uint32_t*)(smem + (AC0H - sbase) + off) = (uint32_t)h0 | ((uint32_t)h1 << 16);
                    *(uint32_t*)(smem + (AC0L - sbase) + off) = (uint32_t)l0 | ((uint32_t)l1 << 16);
                }
            }
        }
    }
    __syncthreads();

    #pragma unroll
    for (int it = 0; it < 6; it++) {
        int i = tid + it * 512;
        if (i >= 3072) break;
        int chunk = i / 1536;
        int rem = i % 1536;
        int r = rem >> 3, cc = rem & 7;
        uint32_t sw = (uint32_t)chunk * 24576 + SWZ128((uint32_t)(r * 128 + cc * 16));
        size_t go = (size_t)r * 128 + chunk * 64 + cc * 8;
        CP_ASYNC16(W1H + sw, W1h + go);
    }
    CP_COMMIT();
    CP_WAIT0();
    __syncthreads();

    const float* sc1p = scAll + 96;
    const float* sh1p = shAll + 96;
    #pragma unroll 1
    for (int nh = 0; nh < 2; nh++) {
        float acc[2][6][4];
        #pragma unroll
        for (int mt = 0; mt < 2; mt++)
            #pragma unroll
            for (int nt = 0; nt < 6; nt++)
                #pragma unroll
                for (int q = 0; q < 4; q++) acc[mt][nt][q] = 0.0f;

        const int arow = wm * 32 + (lane & 15);
        const int browB = nh * 96 + wn * 48 + ((lane >> 4) << 3) + (lane & 7);
        const uint32_t acol = (uint32_t)((lane >> 4) << 4);
        const uint32_t bcol = (uint32_t)(((lane >> 3) & 1) << 4);

        #pragma unroll
        for (int chunk = 0; chunk < 2; chunk++) {
            #pragma unroll
            for (int ks = 0; ks < 4; ks++) {
                uint32_t ah[2][4], al[2][4], bh[6][2];
                #pragma unroll
                for (int mt = 0; mt < 2; mt++) {
                    uint32_t off = (uint32_t)chunk * 32768 +
                        SWZ128((uint32_t)((arow + mt * 16) * 128) + ks * 32 + acol);
                    LDSM_X4(ah[mt], AC0H + off);
                    LDSM_X4(al[mt], AC0L + off);
                }
                #pragma unroll
                for (int p = 0; p < 3; p++) {
                    uint32_t off = (uint32_t)chunk * 24576 +
                        SWZ128((uint32_t)((browB + p * 16) * 128) + ks * 32 + bcol);
                    uint32_t r4[4];
                    LDSM_X4(r4, W1H + off);
                    bh[2 * p][0] = r4[0]; bh[2 * p][1] = r4[1];
                    bh[2 * p + 1][0] = r4[2]; bh[2 * p + 1][1] = r4[3];
                }
                #pragma unroll
                for (int mt = 0; mt < 2; mt++)
                    #pragma unroll
                    for (int nt = 0; nt < 6; nt++) {
                        mma_f16(acc[mt][nt], ah[mt], bh[nt]);
                        mma_f16(acc[mt][nt], al[mt], bh[nt]);
                    }
            }
        }

        #pragma unroll
        for (int nt = 0; nt < 6; nt++) {
            int col = nh * 96 + wn * 48 + nt * 8 + 2 * (lane & 3);
            float sc0 = __ldg(sc1p + col),     sh0 = __ldg(sh1p + col);
            float sc1 = __ldg(sc1p + col + 1), sh1 = __ldg(sh1p + col + 1);
            #pragma unroll
            for (int mt = 0; mt < 2; mt++) {
                int r0 = bm + wm * 32 + mt * 16 + (lane >> 2);
                #pragma unroll
                for (int h = 0; h < 2; h++) {
                    int r = r0 + h * 8;
                    float v0 = fmaxf(fmaf(acc[mt][nt][2 * h],     sc0, sh0), 0.f);
                    float v1 = fmaxf(fmaf(acc[mt][nt][2 * h + 1], sc1, sh1), 0.f);
                    uint16_t h0, l0, h1, l1;
                    split_fp16(v0, h0, l0);
                    split_fp16(v1, h1, l1);
                    size_t ro = (size_t)r * 192 + col;
                    *(uint32_t*)(Ohi + ro) = (uint32_t)h0 | ((uint32_t)h1 << 16);
                    *(uint32_t*)(Olo + ro) = (uint32_t)l0 | ((uint32_t)l1 << 16);
                }
            }
        }
    }
}

// ===== fp16 2-product HMMA GEMM: 128x128 CTA tile, 8 warps, 2 CTAs/SM, K64 2-stage (R13 proven) =====
template<int KPAD, int NACT, int OSTRIDE, int RELU, int FINAL>
__global__ __launch_bounds__(256, 2) void hmma_gemm_kernel(
    const __half* __restrict__ Ahi, const __half* __restrict__ Alo,
    const __half* __restrict__ Bh,
    const float* __restrict__ scale, const float* __restrict__ shift,
    __half* __restrict__ Ohi, __half* __restrict__ Olo,
    float* __restrict__ Ofin)
{
    constexpr int NC = KPAD / 64;
    constexpr int A_BYTES = 128 * 128;
    constexpr int B_BYTES = 128 * 128;
    constexpr int STAGE_BYTES = 2 * A_BYTES + B_BYTES;  // 48KB

    extern __shared__ __align__(1024) char smem[];
    const uint32_t sbase = smem_u32(smem);
    const int tid = threadIdx.x;
    const int wid = tid >> 5;
    const int lane = tid & 31;
    const int wm = wid & 3;
    const int wn = wid >> 2;
    const int bm = blockIdx.y * 128;
    const int bn = blockIdx.x * 128;

    float acc[2][8][4];
    #pragma unroll
    for (int mt = 0; mt < 2; mt++)
        #pragma unroll
        for (int nt = 0; nt < 8; nt++)
            #pragma unroll
            for (int q = 0; q < 4; q++) acc[mt][nt][q] = 0.0f;

    const __half* aHrow = Ahi + (size_t)bm * KPAD;
    const __half* aLrow = Alo + (size_t)bm * KPAD;
    const __half* bHrow = Bh + (size_t)bn * KPAD;

    auto load_stage = [&](int c) {
        const uint32_t so = sbase + (uint32_t)(c & 1) * STAGE_BYTES;
        const int kc = c * 64;
        #pragma unroll
        for (int it = 0; it < 4; it++) {
            int i = tid + it * 256;
            int r = i >> 3, cc = i & 7;
            uint32_t sw = SWZ128((uint32_t)(r * 128 + cc * 16));
            size_t go = (size_t)r * KPAD + kc + cc * 8;
            CP_ASYNC16(so + sw,           aHrow + go);
            CP_ASYNC16(so + A_BYTES + sw, aLrow + go);
        }
        #pragma unroll
        for (int it = 0; it < 4; it++) {
            int i = tid + it * 256;
            int r = i >> 3, cc = i & 7;
            uint32_t sw = SWZ128((uint32_t)(r * 128 + cc * 16));
            size_t go = (size_t)r * KPAD + kc + cc * 8;
            CP_ASYNC16(so + 2 * A_BYTES + sw, bHrow + go);
        }
    };

    load_stage(0);
    CP_COMMIT();

    const int arow = wm * 32 + (lane & 15);
    const int brow = wn * 64 + ((lane >> 4) << 3) + (lane & 7);
    const uint32_t acol = (uint32_t)((lane >> 4) << 4);
    const uint32_t bcol = (uint32_t)(((lane >> 3) & 1) << 4);

    #pragma unroll 1
    for (int c = 0; c < NC; c++) {
        if (c + 1 < NC) { load_stage(c + 1); CP_COMMIT(); CP_WAIT1(); }
        else            { CP_WAIT0(); }
        __syncthreads();

        const uint32_t st = sbase + (uint32_t)(c & 1) * STAGE_BYTES;
        const uint32_t sAh = st, sAl = st + A_BYTES;
        const uint32_t sBh = st + 2 * A_BYTES;

        #pragma unroll
        for (int ks = 0; ks < 4; ks++) {
            uint32_t ah[2][4], al[2][4], bh[8][2];
            #pragma unroll
            for (int mt = 0; mt < 2; mt++) {
                uint32_t off = SWZ128((uint32_t)((arow + mt * 16) * 128) + ks * 32 + acol);
                LDSM_X4(ah[mt], sAh + off);
                LDSM_X4(al[mt], sAl + off);
            }
            #pragma unroll
            for (int p = 0; p < 4; p++) {
                uint32_t off = SWZ128((uint32_t)((brow + p * 16) * 128) + ks * 32 + bcol);
                uint32_t r4[4];
                LDSM_X4(r4, sBh + off);
                bh[2 * p][0] = r4[0]; bh[2 * p][1] = r4[1];
                bh[2 * p + 1][0] = r4[2]; bh[2 * p + 1][1] = r4[3];
            }
            #pragma unroll
            for (int mt = 0; mt < 2; mt++)
                #pragma unroll
                for (int nt = 0; nt < 8; nt++) {
                    mma_f16(acc[mt][nt], ah[mt], bh[nt]);
                    mma_f16(acc[mt][nt], al[mt], bh[nt]);
                }
        }
        __syncthreads();
    }

    if (!FINAL) {
        #pragma unroll
        for (int nt = 0; nt < 8; nt++) {
            int colg = bn + wn * 64 + nt * 8 + 2 * (lane & 3);
            if (colg >= OSTRIDE) continue;
            bool act0 = colg < NACT, act1 = (colg + 1) < NACT;
            float sc0 = act0 ? __ldg(scale + colg) : 0.f;
            float sh0 = act0 ? __ldg(shift + colg) : 0.f;
            float sc1 = act1 ? __ldg(scale + colg + 1) : 0.f;
            float sh1 = act1 ? __ldg(shift + colg + 1) : 0.f;
            #pragma unroll
            for (int mt = 0; mt < 2; mt++) {
                int r0 = bm + wm * 32 + mt * 16 + (lane >> 2);
                #pragma unroll
                for (int h = 0; h < 2; h++) {
                    int r = r0 + h * 8;
                    float v0 = act0 ? fmaf(acc[mt][nt][2 * h],     sc0, sh0) : 0.f;
                    float v1 = act1 ? fmaf(acc[mt][nt][2 * h + 1], sc1, sh1) : 0.f;
                    if (RELU) { v0 = fmaxf(v0, 0.f); v1 = fmaxf(v1, 0.f); }
                    uint16_t h0, l0, h1, l1;
                    split_fp16(v0, h0, l0);
                    split_fp16(v1, h1, l1);
                    size_t ro = (size_t)r * OSTRIDE + colg;
                    *(uint32_t*)(Ohi + ro) = (uint32_t)h0 | ((uint32_t)h1 << 16);
                    *(uint32_t*)(Olo + ro) = (uint32_t)l0 | ((uint32_t)l1 << 16);
                }
            }
        }
    } else {
        float* sf = (float*)smem;            // [128 n][132] floats = 67.6KB < 96KB
        #pragma unroll
        for (int nt = 0; nt < 8; nt++) {
            int coll = wn * 64 + nt * 8 + 2 * (lane & 3);
            int colg = bn + coll;
            float sc0 = __ldg(scale + colg),     sh0 = __ldg(shift + colg);
            float sc1 = __ldg(scale + colg + 1), sh1 = __ldg(shift + colg + 1);
            #pragma unroll
            for (int mt = 0; mt < 2; mt++) {
                int r0 = wm * 32 + mt * 16 + (lane >> 2);
                #pragma unroll
                for (int h = 0; h < 2; h++) {
                    int r = r0 + h * 8;
                    sf[(coll + 0) * 132 + r] = fmaf(acc[mt][nt][2 * h],     sc0, sh0);
                    sf[(coll + 1) * 132 + r] = fmaf(acc[mt][nt][2 * h + 1], sc1, sh1);
                }
            }
        }
        __syncthreads();
        #pragma unroll 1
        for (int i = tid; i < 128 * 128; i += 256) {
            int nl = i >> 7, ml = i & 127;
            int m = bm + ml;
            int b = m / SEGS;
            int s2 = m - b * SEGS;
            Ofin[(size_t)b * 768 * SEGS + (size_t)(bn + nl) * SEGS + s2] = sf[nl * 132 + ml];
        }
    }
}

// ================= launcher =================
extern "C" void kernel_launch(void* const* d_in, const int* in_sizes, int n_in,
                              void* d_out, int out_size)
{
    const float* x      = (const float*)d_in[0];
    const int*   sliced = (const int*)d_in[1];
    PrepArgs pa;
    for (int i = 0; i < 5; i++) {
        int k = 2 + i * 6;
        pa.w[i]  = (const float*)d_in[k + 0];
        pa.bb[i] = (const float*)d_in[k + 1];
        pa.g[i]  = (const float*)d_in[k + 2];
        pa.be[i] = (const float*)d_in[k + 3];
        pa.rm[i] = (const float*)d_in[k + 4];
        pa.rv[i] = (const float*)d_in[k + 5];
    }
    float* out = (float*)d_out;

    void *accP, *h0P, *l0P, *h1P, *l1P, *whP, *scP, *shP;
    cudaGetSymbolAddress(&accP, g_acc);
    cudaGetSymbolAddress(&h0P, g_hi0);
    cudaGetSymbolAddress(&l0P, g_lo0);
    cudaGetSymbolAddress(&h1P, g_hi1);
    cudaGetSymbolAddress(&l1P, g_lo1);
    cudaGetSymbolAddress(&whP, g_wh);
    cudaGetSymbolAddress(&scP, g_scale);
    cudaGetSymbolAddress(&shP, g_shift);
    float* acc = (float*)accP;
    __half* hi0 = (__half*)h0P;
    __half* lo0 = (__half*)l0P;
    __half* hi1 = (__half*)h1P;
    __half* lo1 = (__half*)l1P;
    __half* wh  = (__half*)whP;
    float* sc = (float*)scP;
    float* sh = (float*)shP;

    cudaMemsetAsync(accP, 0, sizeof(float) * 9 * M_ROWS, 0);

    seg_acc_kernel<<<dim3(14, BATCH), SEG_THREADS>>>(x, sliced, out, acc);
    finprep_kernel<<<592, 256>>>(pa, acc, x, hi0, lo0, wh, sc, sh);

    const int WOFF[5] = {0, 8192, 40960, 114688, 409600};
    const int SOFF[5] = {0, 96, 288, 672, 1440};

    const int SMEM_F = 229376;
    cudaFuncSetAttribute(fused01_kernel, cudaFuncAttributeMaxDynamicSharedMemorySize, SMEM_F);
    fused01_kernel<<<dim3(1, 98), 512, SMEM_F>>>(
        hi0, lo0, wh + WOFF[0], wh + WOFF[1], sc, sh, hi1, lo1);

    const int SMEM = 2 * 49152;   // 98304 -> 2 CTAs/SM
    const int MB = M_ROWS / 128;  // 196

    // L2
    cudaFuncSetAttribute(hmma_gemm_kernel<192, 384, 384, 1, 0>,
                         cudaFuncAttributeMaxDynamicSharedMemorySize, SMEM);
    hmma_gemm_kernel<192, 384, 384, 1, 0><<<dim3(3, MB), 256, SMEM>>>(
        hi1, lo1, wh + WOFF[2], sc + SOFF[2], sh + SOFF[2], hi0, lo0, nullptr);

    // L3
    cudaFuncSetAttribute(hmma_gemm_kernel<384, 768, 768, 1, 0>,
                         cudaFuncAttributeMaxDynamicSharedMemorySize, SMEM);
    hmma_gemm_kernel<384, 768, 768, 1, 0><<<dim3(6, MB), 256, SMEM>>>(
        hi0, lo0, wh + WOFF[3], sc + SOFF[3], sh + SOFF[3], hi1, lo1, nullptr);

    // L4 final -> transposed fp32 out
    cudaFuncSetAttribute(hmma_gemm_kernel<768, 768, 768, 0, 1>,
                         cudaFuncAttributeMaxDynamicSharedMemorySize, SMEM);
    hmma_gemm_kernel<768, 768, 768, 0, 1><<<dim3(6, MB), 256, SMEM>>>(
        hi1, lo1, wh + WOFF[4], sc + SOFF[4], sh + SOFF[4], nullptr, nullptr,
        out + OUT_SLICED_ELEMS);
}

// round 17
// speedup vs baseline: 1.2921x; 1.1682x over previous
#include <cuda_runtime.h>
#include <cuda_bf16.h>
#include <cuda_fp16.h>
#include <math.h>
#include <stdint.h>

// ---------------- problem constants ----------------
#define BATCH 128
#define SEGS  196
#define HW    224
#define NPIX  (HW*HW)
#define M_ROWS (BATCH*SEGS)      // 25088 = 128*196
#define BN_EPS 1e-5f
#define OUT_SLICED_ELEMS ((size_t)BATCH*NPIX)

// ================= helpers =================
__device__ __forceinline__ uint32_t smem_u32(const void* p) {
    uint32_t a;
    asm("{ .reg .u64 t; cvta.to.shared.u64 t, %1; cvt.u32.u64 %0, t; }" : "=r"(a) : "l"(p));
    return a;
}
#define SWZ128(off) ((off) ^ (((off) >> 3) & 0x70))

#define CP_ASYNC16(saddr, gptr) \
    asm volatile("cp.async.cg.shared.global [%0], [%1], 16;" :: "r"(saddr), "l"(gptr))
#define CP_COMMIT() asm volatile("cp.async.commit_group;" ::: "memory")
#define CP_WAIT0()  asm volatile("cp.async.wait_group 0;" ::: "memory")
#define CP_WAIT1()  asm volatile("cp.async.wait_group 1;" ::: "memory")

#define LDSM_X4(r, addr) \
    asm volatile("ldmatrix.sync.aligned.m8n8.x4.shared.b16 {%0,%1,%2,%3}, [%4];" \
        : "=r"((r)[0]), "=r"((r)[1]), "=r"((r)[2]), "=r"((r)[3]) : "r"(addr))

__device__ __forceinline__ void mma_f16(float* c, const uint32_t* a, const uint32_t* b) {
    asm volatile(
        "mma.sync.aligned.m16n8k16.row.col.f32.f16.f16.f32 "
        "{%0,%1,%2,%3}, {%4,%5,%6,%7}, {%8,%9}, {%0,%1,%2,%3};"
        : "+f"(c[0]), "+f"(c[1]), "+f"(c[2]), "+f"(c[3])
        : "r"(a[0]), "r"(a[1]), "r"(a[2]), "r"(a[3]), "r"(b[0]), "r"(b[1]));
}

__device__ __forceinline__ void split_fp16(float v, uint16_t& h, uint16_t& l) {
    __half hb = __float2half_rn(v);
    __half lb = __float2half_rn(v - __half2float(hb));
    h = __half_as_ushort(hb);
    l = __half_as_ushort(lb);
}

// ================= scratch (device globals) =================
__device__ float g_acc[9 * M_ROWS];
__device__ __half g_hi0[(size_t)M_ROWS * 768];
__device__ __half g_lo0[(size_t)M_ROWS * 768];
__device__ __half g_hi1[(size_t)M_ROWS * 768];
__device__ __half g_lo1[(size_t)M_ROWS * 768];
__device__ __half g_wh[999424];
__device__ float g_scale[2208];
__device__ float g_shift[2208];

// ================= segment accumulation (R13 proven version) =================
__global__ __launch_bounds__(256) void seg_acc_kernel(
    const float* __restrict__ x, const int* __restrict__ sliced,
    float* __restrict__ outSliced, float* __restrict__ acc)
{
    __shared__ float s[SEGS * 9];
    const int b = blockIdx.y;
    for (int i = threadIdx.x; i < SEGS * 9; i += blockDim.x) s[i] = 0.0f;
    __syncthreads();

    const int chunk = NPIX / gridDim.x;
    const int p0 = blockIdx.x * chunk;
    const float* xb = x + (size_t)b * 3 * NPIX;
    const int* sb = sliced + (size_t)b * NPIX;
    float* ob = outSliced + (size_t)b * NPIX;

    for (int p = p0 + threadIdx.x; p < p0 + chunk; p += blockDim.x) {
        int sid = sb[p];
        ob[p] = (float)sid;
        float r = (float)(p / HW);
        float c = (float)(p % HW);
        float v0 = xb[p], v1 = xb[NPIX + p], v2 = xb[2 * NPIX + p];
        float* a9 = s + sid * 9;
        atomicAdd(a9 + 0, 1.0f);
        atomicAdd(a9 + 1, r);
        atomicAdd(a9 + 2, c);
        atomicAdd(a9 + 3, v0);
        atomicAdd(a9 + 4, v1);
        atomicAdd(a9 + 5, v2);
        atomicAdd(a9 + 6, v0 * v0);
        atomicAdd(a9 + 7, v1 * v1);
        atomicAdd(a9 + 8, v2 * v2);
    }
    __syncthreads();
    for (int i = threadIdx.x; i < SEGS * 9; i += blockDim.x) {
        int sid = i / 9, f = i % 9;
        float v = s[i];
        if (v != 0.0f) atomicAdd(&acc[(size_t)f * M_ROWS + b * SEGS + sid], v);
    }
}

// ================= fused finalize + weight/BN prep =================
struct PrepArgs {
    const float* w[5];
    const float* bb[5];
    const float* g[5];
    const float* be[5];
    const float* rm[5];
    const float* rv[5];
};

__global__ __launch_bounds__(256) void finprep_kernel(
    PrepArgs a, const float* __restrict__ acc, const float* __restrict__ x,
    __half* __restrict__ fhi, __half* __restrict__ flo,
    __half* __restrict__ wh,
    float* __restrict__ sc, float* __restrict__ sh)
{
    const int NLc[5] = {96, 192, 384, 768, 768};
    const int KLc[5] = {11, 96, 192, 384, 768};
    const int KPc[5] = {64, 128, 192, 384, 768};
    const int WOFFc[6] = {0, 8192, 40960, 114688, 409600, 999424};
    const int SOFFc[6] = {0, 96, 288, 672, 1440, 2208};

    const int stride = gridDim.x * blockDim.x;
    const int tid0 = blockIdx.x * blockDim.x + threadIdx.x;

    for (int idx = tid0; idx < M_ROWS; idx += stride) {
        int b = idx / SEGS;
        float cnt  = acc[idx];
        float inv  = 1.0f / fmaxf(cnt, 1.0f);
        float mrow = acc[(size_t)1 * M_ROWS + idx] * inv;
        float mcol = acc[(size_t)2 * M_ROWS + idx] * inv;
        float m0 = acc[(size_t)3 * M_ROWS + idx] * inv;
        float m1 = acc[(size_t)4 * M_ROWS + idx] * inv;
        float m2 = acc[(size_t)5 * M_ROWS + idx] * inv;
        float dn = 1.0f / fmaxf(cnt - 1.0f, 1.0f);
        float v0 = (acc[(size_t)6 * M_ROWS + idx] - cnt * m0 * m0) * dn;
        float v1 = (acc[(size_t)7 * M_ROWS + idx] - cnt * m1 * m1) * dn;
        float v2 = (acc[(size_t)8 * M_ROWS + idx] - cnt * m2 * m2) * dn;
        float sd0 = (cnt > 1.0f) ? sqrtf(fmaxf(v0, 0.0f)) : 0.0f;
        float sd1 = (cnt > 1.0f) ? sqrtf(fmaxf(v1, 0.0f)) : 0.0f;
        float sd2 = (cnt > 1.0f) ? sqrtf(fmaxf(v2, 0.0f)) : 0.0f;

        int ri = min(max((int)mrow, 0), HW - 1);
        int ci = min(max((int)mcol, 0), HW - 1);
        const float* xb = x + (size_t)b * 3 * NPIX;
        int pp = ri * HW + ci;
        float mask = (cnt > 0.0f) ? 1.0f : 0.0f;

        float f[11];
        f[0] = mrow * mask; f[1] = mcol * mask;
        f[2] = m0 * mask;   f[3] = m1 * mask;   f[4] = m2 * mask;
        f[5] = sd0 * mask;  f[6] = sd1 * mask;  f[7] = sd2 * mask;
        f[8] = xb[pp] * mask; f[9] = xb[NPIX + pp] * mask; f[10] = xb[2 * NPIX + pp] * mask;

        __half* ph = fhi + (size_t)idx * 64;
        __half* pl = flo + (size_t)idx * 64;
        #pragma unroll
        for (int c = 0; c < 11; c++) {
            __half h = __float2half_rn(f[c]);
            ph[c] = h;
            pl[c] = __float2half_rn(f[c] - __half2float(h));
        }
        for (int c = 11; c < 64; c++) { ph[c] = __float2half_rn(0.f); pl[c] = __float2half_rn(0.f); }
    }

    for (int i = tid0; i < 999424; i += stride) {
        int L = 0;
        while (i >= WOFFc[L + 1]) L++;
        int off = i - WOFFc[L];
        int n = off / KPc[L], k = off - n * KPc[L];
        float v = (n < NLc[L] && k < KLc[L]) ? a.w[L][n * KLc[L] + k] : 0.0f;
        wh[i] = __float2half_rn(v);
    }
    for (int i = tid0; i < 2208; i += stride) {
        int L = 0;
        while (i >= SOFFc[L + 1]) L++;
        int n = i - SOFFc[L];
        float s = a.g[L][n] * rsqrtf(a.rv[L][n] + BN_EPS);
        sc[i] = s;
        sh[i] = (a.bb[L][n] - a.rm[L][n]) * s + a.be[L][n];
    }
}

// ================= fused L0+L1 kernel (fp16 2-product, unchanged) =================
__global__ __launch_bounds__(512, 1) void fused01_kernel(
    const __half* __restrict__ Fhi, const __half* __restrict__ Flo,
    const __half* __restrict__ W0h, const __half* __restrict__ W1h,
    const float* __restrict__ scAll, const float* __restrict__ shAll,
    __half* __restrict__ Ohi, __half* __restrict__ Olo)
{
    extern __shared__ __align__(1024) char smem[];
    const uint32_t sbase = smem_u32(smem);
    const int tid = threadIdx.x;
    const int wid = tid >> 5;
    const int lane = tid & 31;
    const int wm = wid & 7;
    const int wn = wid >> 3;
    const int bm = blockIdx.y * 256;

    const uint32_t F_AH = sbase, F_AL = sbase + 32768;
    const uint32_t W0H = sbase + 65536;
    const uint32_t AC0H = sbase + 98304, AC0L = sbase + 163840;
    const uint32_t W1H = sbase;

    #pragma unroll
    for (int it = 0; it < 4; it++) {
        int i = tid + it * 512;
        int r = i >> 3, cc = i & 7;
        uint32_t sw = SWZ128((uint32_t)(r * 128 + cc * 16));
        size_t go = (size_t)(bm + r) * 64 + cc * 8;
        CP_ASYNC16(F_AH + sw, Fhi + go);
        CP_ASYNC16(F_AL + sw, Flo + go);
    }
    #pragma unroll
    for (int it = 0; it < 2; it++) {
        int i = tid + it * 512;
        int r = i >> 3, cc = i & 7;
        uint32_t sw = SWZ128((uint32_t)(r * 128 + cc * 16));
        size_t go = (size_t)r * 64 + cc * 8;
        CP_ASYNC16(W0H + sw, W0h + go);
    }
    CP_COMMIT();
    CP_WAIT0();
    __syncthreads();

    {
        float acc[2][8][4];
        #pragma unroll
        for (int mt = 0; mt < 2; mt++)
            #pragma unroll
            for (int nt = 0; nt < 8; nt++)
                #pragma unroll
                for (int q = 0; q < 4; q++) acc[mt][nt][q] = 0.0f;

        const int arow = wm * 32 + (lane & 15);
        const int brow = wn * 64 + ((lane >> 4) << 3) + (lane & 7);
        const uint32_t acol = (uint32_t)((lane >> 4) << 4);
        const uint32_t bcol = (uint32_t)(((lane >> 3) & 1) << 4);

        #pragma unroll
        for (int ks = 0; ks < 4; ks++) {
            uint32_t ah[2][4], al[2][4], bh[8][2];
            #pragma unroll
            for (int mt = 0; mt < 2; mt++) {
                uint32_t off = SWZ128((uint32_t)((arow + mt * 16) * 128) + ks * 32 + acol);
                LDSM_X4(ah[mt], F_AH + off);
                LDSM_X4(al[mt], F_AL + off);
            }
            #pragma unroll
            for (int p = 0; p < 4; p++) {
                uint32_t off = SWZ128((uint32_t)((brow + p * 16) * 128) + ks * 32 + bcol);
                uint32_t r4[4];
                LDSM_X4(r4, W0H + off);
                bh[2 * p][0] = r4[0]; bh[2 * p][1] = r4[1];
                bh[2 * p + 1][0] = r4[2]; bh[2 * p + 1][1] = r4[3];
            }
            #pragma unroll
            for (int mt = 0; mt < 2; mt++)
                #pragma unroll
                for (int nt = 0; nt < 8; nt++) {
                    mma_f16(acc[mt][nt], ah[mt], bh[nt]);
                    mma_f16(acc[mt][nt], al[mt], bh[nt]);
                }
        }

        #pragma unroll
        for (int nt = 0; nt < 8; nt++) {
            int col = wn * 64 + nt * 8 + 2 * (lane & 3);
            bool act0v = col < 96, act1v = (col + 1) < 96;
            float sc0 = act0v ? __ldg(scAll + col) : 0.f;
            float sh0 = act0v ? __ldg(shAll + col) : 0.f;
            float sc1 = act1v ? __ldg(scAll + col + 1) : 0.f;
            float sh1 = act1v ? __ldg(shAll + col + 1) : 0.f;
            int chunk = col >> 6;
            int ccol = col & 63;
            #pragma unroll
            for (int mt = 0; mt < 2; mt++) {
                int r0 = wm * 32 + mt * 16 + (lane >> 2);
                #pragma unroll
                for (int h = 0; h < 2; h++) {
                    int r = r0 + h * 8;
                    float v0 = act0v ? fmaxf(fmaf(acc[mt][nt][2 * h],     sc0, sh0), 0.f) : 0.f;
                    float v1 = act1v ? fmaxf(fmaf(acc[mt][nt][2 * h + 1], sc1, sh1), 0.f) : 0.f;
                    uint16_t h0, l0, h1, l1;
                    split_fp16(v0, h0, l0);
                    split_fp16(v1, h1, l1);
                    uint32_t off = (uint32_t)chunk * 32768 + SWZ128((uint32_t)(r * 128 + ccol * 2));
                    *(uint32_t*)(smem + (AC0H - sbase) + off) = (uint32_t)h0 | ((uint32_t)h1 << 16);
                    *(uint32_t*)(smem + (AC0L - sbase) + off) = (uint32_t)l0 | ((uint32_t)l1 << 16);
                }
            }
        }
    }
    __syncthreads();

    #pragma unroll
    for (int it = 0; it < 6; it++) {
        int i = tid + it * 512;
        if (i >= 3072) break;
        int chunk = i / 1536;
        int rem = i % 1536;
        int r = rem >> 3, cc = rem & 7;
        uint32_t sw = (uint32_t)chunk * 24576 + SWZ128((uint32_t)(r * 128 + cc * 16));
        size_t go = (size_t)r * 128 + chunk * 64 + cc * 8;
        CP_ASYNC16(W1H + sw, W1h + go);
    }
    CP_COMMIT();
    CP_WAIT0();
    __syncthreads();

    const float* sc1p = scAll + 96;
    const float* sh1p = shAll + 96;
    #pragma unroll 1
    for (int nh = 0; nh < 2; nh++) {
        float acc[2][6][4];
        #pragma unroll
        for (int mt = 0; mt < 2; mt++)
            #pragma unroll
            for (int nt = 0; nt < 6; nt++)
                #pragma unroll
                for (int q = 0; q < 4; q++) acc[mt][nt][q] = 0.0f;

        const int arow = wm * 32 + (lane & 15);
        const int browB = nh * 96 + wn * 48 + ((lane >> 4) << 3) + (lane & 7);
        const uint32_t acol = (uint32_t)((lane >> 4) << 4);
        const uint32_t bcol = (uint32_t)(((lane >> 3) & 1) << 4);

        #pragma unroll
        for (int chunk = 0; chunk < 2; chunk++) {
            #pragma unroll
            for (int ks = 0; ks < 4; ks++) {
                uint32_t ah[2][4], al[2][4], bh[6][2];
                #pragma unroll
                for (int mt = 0; mt < 2; mt++) {
                    uint32_t off = (uint32_t)chunk * 32768 +
                        SWZ128((uint32_t)((arow + mt * 16) * 128) + ks * 32 + acol);
                    LDSM_X4(ah[mt], AC0H + off);
                    LDSM_X4(al[mt], AC0L + off);
                }
                #pragma unroll
                for (int p = 0; p < 3; p++) {
                    uint32_t off = (uint32_t)chunk * 24576 +
                        SWZ128((uint32_t)((browB + p * 16) * 128) + ks * 32 + bcol);
                    uint32_t r4[4];
                    LDSM_X4(r4, W1H + off);
                    bh[2 * p][0] = r4[0]; bh[2 * p][1] = r4[1];
                    bh[2 * p + 1][0] = r4[2]; bh[2 * p + 1][1] = r4[3];
                }
                #pragma unroll
                for (int mt = 0; mt < 2; mt++)
                    #pragma unroll
                    for (int nt = 0; nt < 6; nt++) {
                        mma_f16(acc[mt][nt], ah[mt], bh[nt]);
                        mma_f16(acc[mt][nt], al[mt], bh[nt]);
                    }
            }
        }

        #pragma unroll
        for (int nt = 0; nt < 6; nt++) {
            int col = nh * 96 + wn * 48 + nt * 8 + 2 * (lane & 3);
            float sc0 = __ldg(sc1p + col),     sh0 = __ldg(sh1p + col);
            float sc1 = __ldg(sc1p + col + 1), sh1 = __ldg(sh1p + col + 1);
            #pragma unroll
            for (int mt = 0; mt < 2; mt++) {
                int r0 = bm + wm * 32 + mt * 16 + (lane >> 2);
                #pragma unroll
                for (int h = 0; h < 2; h++) {
                    int r = r0 + h * 8;
                    float v0 = fmaxf(fmaf(acc[mt][nt][2 * h],     sc0, sh0), 0.f);
                    float v1 = fmaxf(fmaf(acc[mt][nt][2 * h + 1], sc1, sh1), 0.f);
                    uint16_t h0, l0, h1, l1;
                    split_fp16(v0, h0, l0);
                    split_fp16(v1, h1, l1);
                    size_t ro = (size_t)r * 192 + col;
                    *(uint32_t*)(Ohi + ro) = (uint32_t)h0 | ((uint32_t)h1 << 16);
                    *(uint32_t*)(Olo + ro) = (uint32_t)l0 | ((uint32_t)l1 << 16);
                }
            }
        }
    }
}

// ===== fp16 HMMA GEMM: 128x128 CTA tile, 8 warps, 2 CTAs/SM, K64 2-stage (R13 proven) =====
// NPROD = 2: C = (Ah+Al)*Bh ; NPROD = 1: C = Ah*Bh (output layer only)
template<int KPAD, int NACT, int OSTRIDE, int RELU, int FINAL, int NPROD>
__global__ __launch_bounds__(256, 2) void hmma_gemm_kernel(
    const __half* __restrict__ Ahi, const __half* __restrict__ Alo,
    const __half* __restrict__ Bh,
    const float* __restrict__ scale, const float* __restrict__ shift,
    __half* __restrict__ Ohi, __half* __restrict__ Olo,
    float* __restrict__ Ofin)
{
    constexpr int NC = KPAD / 64;
    constexpr int A_BYTES = 128 * 128;
    constexpr int B_BYTES = 128 * 128;
    constexpr int STAGE_BYTES = 2 * A_BYTES + B_BYTES;  // 48KB

    extern __shared__ __align__(1024) char smem[];
    const uint32_t sbase = smem_u32(smem);
    const int tid = threadIdx.x;
    const int wid = tid >> 5;
    const int lane = tid & 31;
    const int wm = wid & 3;
    const int wn = wid >> 2;
    const int bm = blockIdx.y * 128;
    const int bn = blockIdx.x * 128;

    float acc[2][8][4];
    #pragma unroll
    for (int mt = 0; mt < 2; mt++)
        #pragma unroll
        for (int nt = 0; nt < 8; nt++)
            #pragma unroll
            for (int q = 0; q < 4; q++) acc[mt][nt][q] = 0.0f;

    const __half* aHrow = Ahi + (size_t)bm * KPAD;
    const __half* aLrow = Alo + (size_t)bm * KPAD;
    const __half* bHrow = Bh + (size_t)bn * KPAD;

    auto load_stage = [&](int c) {
        const uint32_t so = sbase + (uint32_t)(c & 1) * STAGE_BYTES;
        const int kc = c * 64;
        #pragma unroll
        for (int it = 0; it < 4; it++) {
            int i = tid + it * 256;
            int r = i >> 3, cc = i & 7;
            uint32_t sw = SWZ128((uint32_t)(r * 128 + cc * 16));
            size_t go = (size_t)r * KPAD + kc + cc * 8;
            CP_ASYNC16(so + sw, aHrow + go);
            if (NPROD == 2) CP_ASYNC16(so + A_BYTES + sw, aLrow + go);
        }
        #pragma unroll
        for (int it = 0; it < 4; it++) {
            int i = tid + it * 256;
            int r = i >> 3, cc = i & 7;
            uint32_t sw = SWZ128((uint32_t)(r * 128 + cc * 16));
            size_t go = (size_t)r * KPAD + kc + cc * 8;
            CP_ASYNC16(so + 2 * A_BYTES + sw, bHrow + go);
        }
    };

    load_stage(0);
    CP_COMMIT();

    const int arow = wm * 32 + (lane & 15);
    const int brow = wn * 64 + ((lane >> 4) << 3) + (lane & 7);
    const uint32_t acol = (uint32_t)((lane >> 4) << 4);
    const uint32_t bcol = (uint32_t)(((lane >> 3) & 1) << 4);

    #pragma unroll 1
    for (int c = 0; c < NC; c++) {
        if (c + 1 < NC) { load_stage(c + 1); CP_COMMIT(); CP_WAIT1(); }
        else            { CP_WAIT0(); }
        __syncthreads();

        const uint32_t st = sbase + (uint32_t)(c & 1) * STAGE_BYTES;
        const uint32_t sAh = st, sAl = st + A_BYTES;
        const uint32_t sBh = st + 2 * A_BYTES;

        #pragma unroll
        for (int ks = 0; ks < 4; ks++) {
            uint32_t ah[2][4], al[2][4], bh[8][2];
            #pragma unroll
            for (int mt = 0; mt < 2; mt++) {
                uint32_t off = SWZ128((uint32_t)((arow + mt * 16) * 128) + ks * 32 + acol);
                LDSM_X4(ah[mt], sAh + off);
                if (NPROD == 2) LDSM_X4(al[mt], sAl + off);
            }
            #pragma unroll
            for (int p = 0; p < 4; p++) {
                uint32_t off = SWZ128((uint32_t)((brow + p * 16) * 128) + ks * 32 + bcol);
                uint32_t r4[4];
                LDSM_X4(r4, sBh + off);
                bh[2 * p][0] = r4[0]; bh[2 * p][1] = r4[1];
                bh[2 * p + 1][0] = r4[2]; bh[2 * p + 1][1] = r4[3];
            }
            #pragma unroll
            for (int mt = 0; mt < 2; mt++)
                #pragma unroll
                for (int nt = 0; nt < 8; nt++) {
                    mma_f16(acc[mt][nt], ah[mt], bh[nt]);
                    if (NPROD == 2) mma_f16(acc[mt][nt], al[mt], bh[nt]);
                }
        }
        __syncthreads();
    }

    if (!FINAL) {
        #pragma unroll
        for (int nt = 0; nt < 8; nt++) {
            int colg = bn + wn * 64 + nt * 8 + 2 * (lane & 3);
            if (colg >= OSTRIDE) continue;
            bool act0 = colg < NACT, act1 = (colg + 1) < NACT;
            float sc0 = act0 ? __ldg(scale + colg) : 0.f;
            float sh0 = act0 ? __ldg(shift + colg) : 0.f;
            float sc1 = act1 ? __ldg(scale + colg + 1) : 0.f;
            float sh1 = act1 ? __ldg(shift + colg + 1) : 0.f;
            #pragma unroll
            for (int mt = 0; mt < 2; mt++) {
                int r0 = bm + wm * 32 + mt * 16 + (lane >> 2);
                #pragma unroll
                for (int h = 0; h < 2; h++) {
                    int r = r0 + h * 8;
                    float v0 = act0 ? fmaf(acc[mt][nt][2 * h],     sc0, sh0) : 0.f;
                    float v1 = act1 ? fmaf(acc[mt][nt][2 * h + 1], sc1, sh1) : 0.f;
                    if (RELU) { v0 = fmaxf(v0, 0.f); v1 = fmaxf(v1, 0.f); }
                    uint16_t h0, l0, h1, l1;
                    split_fp16(v0, h0, l0);
                    split_fp16(v1, h1, l1);
                    size_t ro = (size_t)r * OSTRIDE + colg;
                    *(uint32_t*)(Ohi + ro) = (uint32_t)h0 | ((uint32_t)h1 << 16);
                    *(uint32_t*)(Olo + ro) = (uint32_t)l0 | ((uint32_t)l1 << 16);
                }
            }
        }
    } else {
        float* sf = (float*)smem;            // [128 n][132] floats = 67.6KB < 96KB
        #pragma unroll
        for (int nt = 0; nt < 8; nt++) {
            int coll = wn * 64 + nt * 8 + 2 * (lane & 3);
            int colg = bn + coll;
            float sc0 = __ldg(scale + colg),     sh0 = __ldg(shift + colg);
            float sc1 = __ldg(scale + colg + 1), sh1 = __ldg(shift + colg + 1);
            #pragma unroll
            for (int mt = 0; mt < 2; mt++) {
                int r0 = wm * 32 + mt * 16 + (lane >> 2);
                #pragma unroll
                for (int h = 0; h < 2; h++) {
                    int r = r0 + h * 8;
                    sf[(coll + 0) * 132 + r] = fmaf(acc[mt][nt][2 * h],     sc0, sh0);
                    sf[(coll + 1) * 132 + r] = fmaf(acc[mt][nt][2 * h + 1], sc1, sh1);
                }
            }
        }
        __syncthreads();
        #pragma unroll 1
        for (int i = tid; i < 128 * 128; i += 256) {
            int nl = i >> 7, ml = i & 127;
            int m = bm + ml;
            int b = m / SEGS;
            int s2 = m - b * SEGS;
            Ofin[(size_t)b * 768 * SEGS + (size_t)(bn + nl) * SEGS + s2] = sf[nl * 132 + ml];
        }
    }
}

// ================= launcher =================
extern "C" void kernel_launch(void* const* d_in, const int* in_sizes, int n_in,
                              void* d_out, int out_size)
{
    const float* x      = (const float*)d_in[0];
    const int*   sliced = (const int*)d_in[1];
    PrepArgs pa;
    for (int i = 0; i < 5; i++) {
        int k = 2 + i * 6;
        pa.w[i]  = (const float*)d_in[k + 0];
        pa.bb[i] = (const float*)d_in[k + 1];
        pa.g[i]  = (const float*)d_in[k + 2];
        pa.be[i] = (const float*)d_in[k + 3];
        pa.rm[i] = (const float*)d_in[k + 4];
        pa.rv[i] = (const float*)d_in[k + 5];
    }
    float* out = (float*)d_out;

    void *accP, *h0P, *l0P, *h1P, *l1P, *whP, *scP, *shP;
    cudaGetSymbolAddress(&accP, g_acc);
    cudaGetSymbolAddress(&h0P, g_hi0);
    cudaGetSymbolAddress(&l0P, g_lo0);
    cudaGetSymbolAddress(&h1P, g_hi1);
    cudaGetSymbolAddress(&l1P, g_lo1);
    cudaGetSymbolAddress(&whP, g_wh);
    cudaGetSymbolAddress(&scP, g_scale);
    cudaGetSymbolAddress(&shP, g_shift);
    float* acc = (float*)accP;
    __half* hi0 = (__half*)h0P;
    __half* lo0 = (__half*)l0P;
    __half* hi1 = (__half*)h1P;
    __half* lo1 = (__half*)l1P;
    __half* wh  = (__half*)whP;
    float* sc = (float*)scP;
    float* sh = (float*)shP;

    cudaMemsetAsync(accP, 0, sizeof(float) * 9 * M_ROWS, 0);

    seg_acc_kernel<<<dim3(8, BATCH), 256>>>(x, sliced, out, acc);
    finprep_kernel<<<592, 256>>>(pa, acc, x, hi0, lo0, wh, sc, sh);

    const int WOFF[5] = {0, 8192, 40960, 114688, 409600};
    const int SOFF[5] = {0, 96, 288, 672, 1440};

    const int SMEM_F = 229376;
    cudaFuncSetAttribute(fused01_kernel, cudaFuncAttributeMaxDynamicSharedMemorySize, SMEM_F);
    fused01_kernel<<<dim3(1, 98), 512, SMEM_F>>>(
        hi0, lo0, wh + WOFF[0], wh + WOFF[1], sc, sh, hi1, lo1);

    const int SMEM = 2 * 49152;   // 98304 -> 2 CTAs/SM
    const int MB = M_ROWS / 128;  // 196

    // L2 (NPROD=2)
    cudaFuncSetAttribute(hmma_gemm_kernel<192, 384, 384, 1, 0, 2>,
                         cudaFuncAttributeMaxDynamicSharedMemorySize, SMEM);
    hmma_gemm_kernel<192, 384, 384, 1, 0, 2><<<dim3(3, MB), 256, SMEM>>>(
        hi1, lo1, wh + WOFF[2], sc + SOFF[2], sh + SOFF[2], hi0, lo0, nullptr);

    // L3 (NPROD=2)
    cudaFuncSetAttribute(hmma_gemm_kernel<384, 768, 768, 1, 0, 2>,
                         cudaFuncAttributeMaxDynamicSharedMemorySize, SMEM);
    hmma_gemm_kernel<384, 768, 768, 1, 0, 2><<<dim3(6, MB), 256, SMEM>>>(
        hi0, lo0, wh + WOFF[3], sc + SOFF[3], sh + SOFF[3], hi1, lo1, nullptr);

    // L4 final (NPROD=1, output layer: error not amplified downstream)
    cudaFuncSetAttribute(hmma_gemm_kernel<768, 768, 768, 0, 1, 1>,
                         cudaFuncAttributeMaxDynamicSharedMemorySize, SMEM);
    hmma_gemm_kernel<768, 768, 768, 0, 1, 1><<<dim3(6, MB), 256, SMEM>>>(
        hi1, lo1, wh + WOFF[4], sc + SOFF[4], sh + SOFF[4], nullptr, nullptr,
        out + OUT_SLICED_ELEMS);
}